// round 11
// baseline (speedup 1.0000x reference)
#include <cuda_runtime.h>
#include <cuda_fp16.h>
#include <math.h>
#include <stdint.h>

#define BATCH 32
#define TLEN  512
#define INDIM 128
#define RES   2048
#define OUTD  64
#define NWIN  128
#define MROWS (BATCH*NWIN)   /* 4096  reservoir rows (b,w) */
#define NROWS (BATCH*TLEN)   /* 16384 time rows (b,t)      */

/* ---------------- scratch (device globals; no allocations) ---------------- */
__device__ float g_A[BATCH * TLEN * TLEN]; /* gram matrices          32 MB */
__device__ float g_LT[BATCH * TLEN * TLEN];/* L transposed           32 MB */
__device__ float g_Z[BATCH * TLEN * OUTD]; /* solve result            4 MB */
/* fp16 split planes (hi+lo reconstructs fp32 to ~2^-22) */
__device__ half g_Shi0[MROWS * RES], g_Slo0[MROWS * RES];   /* state ping */
__device__ half g_Shi1[MROWS * RES], g_Slo1[MROWS * RES];   /* state pong */
__device__ half g_rshi[NROWS * RES], g_rslo[NROWS * RES];   /* rs states  */
__device__ half g_iphi[NROWS * RES], g_iplo[NROWS * RES];   /* inproj     */
__device__ half g_Whi[RES * RES],   g_Wlo[RES * RES];       /* WresT      */
__device__ half g_WinHi[RES * INDIM], g_WinLo[RES * INDIM]; /* WinT       */
__device__ half g_xhi[NROWS * INDIM], g_xlo[NROWS * INDIM]; /* input      */

/* ====================== helpers ====================== */
__device__ __forceinline__ uint32_t smem_u32(const void* p) {
    uint32_t a;
    asm("{ .reg .u64 t; cvta.to.shared.u64 t, %1; cvt.u32.u64 %0, t; }" : "=r"(a) : "l"(p));
    return a;
}
__device__ __forceinline__ void cpasync16(uint32_t dst, const void* src) {
    asm volatile("cp.async.cg.shared.global [%0], [%1], 16;" :: "r"(dst), "l"(src));
}
__device__ __forceinline__ void cp_commit() { asm volatile("cp.async.commit_group;" ::: "memory"); }
__device__ __forceinline__ void cp_wait1()  { asm volatile("cp.async.wait_group 1;" ::: "memory"); }
__device__ __forceinline__ void cp_wait0()  { asm volatile("cp.async.wait_group 0;" ::: "memory"); }

__device__ __forceinline__ void ldsm4(uint32_t* r, uint32_t addr) {
    asm volatile("ldmatrix.sync.aligned.m8n8.x4.shared.b16 {%0,%1,%2,%3}, [%4];"
        : "=r"(r[0]), "=r"(r[1]), "=r"(r[2]), "=r"(r[3]) : "r"(addr));
}
__device__ __forceinline__ void mma16816(float* d, const uint32_t* a, uint32_t b0, uint32_t b1) {
    asm volatile(
        "mma.sync.aligned.m16n8k16.row.col.f32.f16.f16.f32 "
        "{%0,%1,%2,%3},{%4,%5,%6,%7},{%8,%9},{%0,%1,%2,%3};"
        : "+f"(d[0]), "+f"(d[1]), "+f"(d[2]), "+f"(d[3])
        : "r"(a[0]), "r"(a[1]), "r"(a[2]), "r"(a[3]), "r"(b0), "r"(b1));
}
__device__ __forceinline__ void split16(float f, half& h, half& l) {
    h = __float2half_rn(f);
    l = __float2half_rn(f - __half2float(h));
}
__device__ __forceinline__ float2 rec2(half2 h, half2 l) {
    float2 fh = __half22float2(h), fl = __half22float2(l);
    return make_float2(fh.x + fl.x, fh.y + fl.y);
}

/* ============ fp16x3 GEMM kernel (mma.sync m16n8k16) ====================== */
#define A_PLANE 8192
#define B_PLANE 8192
#define STAGE_B 32768
#define SMEM_DYN (3*STAGE_B)   /* 98304 */

__global__ __launch_bounds__(256, 2) void tc_kernel(
    int mode, int s, int flip, const float* __restrict__ lam)
{
    extern __shared__ char smem[];
    const uint32_t smem_u = smem_u32(smem);

    const int tid = threadIdx.x;
    const int wid = tid >> 5, lane = tid & 31;
    const int gid = lane >> 2, tig = lane & 3;
    const int m = lane >> 3, l7 = lane & 7;
    const int warpM = wid >> 2, warpN = wid & 3;
    const int rowBase = warpM * 64, colBase = warpN * 32;

    int row0, col0;
    if (mode == 1) {
        int x = blockIdx.x, ti = 0;
        while ((ti + 1) * (ti + 2) / 2 <= x) ti++;
        int tj = x - ti * (ti + 1) / 2;
        row0 = ti * 128; col0 = tj * 128;
    } else {
        row0 = blockIdx.y * 128; col0 = blockIdx.x * 128;
    }

    const half *Ahi, *Alo, *Bhi, *Blo; int K;
    if (mode == 0) {
        Ahi = flip ? g_Shi1 : g_Shi0; Alo = flip ? g_Slo1 : g_Slo0;
        Bhi = g_Whi; Blo = g_Wlo; K = RES;
    } else if (mode == 1) {
        size_t base = (size_t)blockIdx.z * TLEN * RES;
        Ahi = g_rshi + base; Alo = g_rslo + base;
        Bhi = Ahi; Blo = Alo; K = RES;
    } else {
        Ahi = g_xhi; Alo = g_xlo; Bhi = g_WinHi; Blo = g_WinLo; K = INDIM;
    }
    const int nIter = K >> 5;

    float acc[4][4][4] = {};

    uint32_t aRB[4], aX[4], bRB[2], bX[2];
    #pragma unroll
    for (int mt = 0; mt < 4; mt++) {
        uint32_t r = rowBase + mt * 16 + (m & 1) * 8 + l7;
        aRB[mt] = r * 64; aX[mt] = (r >> 1) & 3;
    }
    #pragma unroll
    for (int np = 0; np < 2; np++) {
        uint32_t n = colBase + (np * 2 + (m >> 1)) * 8 + l7;
        bRB[np] = n * 64; bX[np] = (n >> 1) & 3;
    }
    const uint32_t amk = (uint32_t)(m >> 1);
    const uint32_t bmk = (uint32_t)(m & 1);

    auto load_chunk = [&](int it, int stage) {
        const int k0 = it << 5;
        const uint32_t sb = smem_u + (uint32_t)stage * STAGE_B;
        #pragma unroll
        for (int q = 0; q < 8; q++) {
            int idx = tid + q * 256;
            int op = idx >> 10;
            int j = idx & 1023;
            int p = j >> 9, r = (j >> 2) & 127, c = j & 3;
            const half* gp = op ? (p ? Blo : Bhi) : (p ? Alo : Ahi);
            int rowg = (op ? col0 : row0) + r;
            const half* src = gp + (size_t)rowg * K + k0 + c * 8;
            uint32_t dst = sb + (uint32_t)op * (2 * A_PLANE) + (uint32_t)p * A_PLANE
                         + (uint32_t)r * 64 + (uint32_t)((c ^ ((r >> 1) & 3)) * 16);
            cpasync16(dst, src);
        }
    };

    load_chunk(0, 0);
    cp_commit();
    if (nIter > 1) { load_chunk(1, 1); cp_commit(); }

    for (int it = 0; it < nIter; ++it) {
        if (it + 1 < nIter) cp_wait1(); else cp_wait0();
        __syncthreads();
        if (it + 2 < nIter) { load_chunk(it + 2, (it + 2) % 3); cp_commit(); }

        const uint32_t sb = smem_u + (uint32_t)(it % 3) * STAGE_B;
        const uint32_t pAh = sb, pAl = sb + A_PLANE;
        const uint32_t pBh = sb + 2 * A_PLANE, pBl = pBh + B_PLANE;
        #pragma unroll
        for (int h16 = 0; h16 < 2; h16++) {
            uint32_t bh[2][4], bl[2][4];
            #pragma unroll
            for (int np = 0; np < 2; np++) {
                uint32_t off = bRB[np] + (((h16 * 2 + bmk) ^ bX[np]) * 16);
                ldsm4(bh[np], pBh + off);
                ldsm4(bl[np], pBl + off);
            }
            #pragma unroll
            for (int mt = 0; mt < 4; mt++) {
                uint32_t ah[4], al[4];
                uint32_t off = aRB[mt] + (((h16 * 2 + amk) ^ aX[mt]) * 16);
                ldsm4(ah, pAh + off);
                ldsm4(al, pAl + off);
                #pragma unroll
                for (int nt = 0; nt < 4; nt++) {
                    uint32_t b0h = bh[nt >> 1][(nt & 1) * 2], b1h = bh[nt >> 1][(nt & 1) * 2 + 1];
                    uint32_t b0l = bl[nt >> 1][(nt & 1) * 2], b1l = bl[nt >> 1][(nt & 1) * 2 + 1];
                    mma16816(acc[mt][nt], ah, b0h, b1h);
                    mma16816(acc[mt][nt], ah, b0l, b1l);
                    mma16816(acc[mt][nt], al, b0h, b1h);
                }
            }
        }
    }

    /* -------------------- epilogue (register -> global, planes only) ------- */
    float regc = 0.f;
    if (mode == 1) { float l = lam[0]; regc = log1pf(expf(l)); }
    const half* SoHi = flip ? g_Shi1 : g_Shi0;
    const half* SoLo = flip ? g_Slo1 : g_Slo0;
    half* ShiN = flip ? g_Shi0 : g_Shi1;
    half* SloN = flip ? g_Slo0 : g_Slo1;

    #pragma unroll
    for (int mt = 0; mt < 4; mt++)
        #pragma unroll
        for (int nt = 0; nt < 4; nt++)
            #pragma unroll
            for (int h = 0; h < 2; h++) {
                int grow = row0 + rowBase + mt * 16 + gid + h * 8;
                int col = col0 + colBase + nt * 8 + tig * 2;
                float cx = acc[mt][nt][h * 2 + 0];
                float cy = acc[mt][nt][h * 2 + 1];
                if (mode == 0) {
                    int b = grow >> 7, w = grow & 127;
                    int t = 4 * w + s - 2;
                    size_t so_off = (size_t)grow * RES + col;
                    float2 so = rec2(*(const half2*)&SoHi[so_off],
                                     *(const half2*)&SoLo[so_off]);
                    float2 u = make_float2(0.f, 0.f);
                    if (t >= 0) {
                        size_t uo = ((size_t)(b << 9) + t) * RES + col;
                        u = rec2(*(const half2*)&g_iphi[uo], *(const half2*)&g_iplo[uo]);
                    }
                    float2 v;
                    v.x = 0.7f * so.x + 0.3f * sinf(cx + u.x);
                    v.y = 0.7f * so.y + 0.3f * sinf(cy + u.y);
                    half hx, lx, hy, ly;
                    split16(v.x, hx, lx); split16(v.y, hy, ly);
                    *(half2*)&ShiN[so_off] = __halves2half2(hx, hy);
                    *(half2*)&SloN[so_off] = __halves2half2(lx, ly);
                    if (s >= 2) {
                        size_t ro = ((size_t)(b << 9) + t) * RES + col;
                        *(half2*)&g_rshi[ro] = __halves2half2(hx, hy);
                        *(half2*)&g_rslo[ro] = __halves2half2(lx, ly);
                    }
                } else if (mode == 1) {
                    float* Abm = g_A + (size_t)blockIdx.z * TLEN * TLEN;
                    float2 v;
                    v.x = cx + 1.0f + ((grow == col + 0) ? regc : 0.f);
                    v.y = cy + 1.0f + ((grow == col + 1) ? regc : 0.f);
                    *(float2*)&Abm[(size_t)grow * TLEN + col] = v;
                } else {
                    half hx, lx, hy, ly;
                    split16(cx, hx, lx); split16(cy, hy, ly);
                    size_t off = (size_t)grow * RES + col;
                    *(half2*)&g_iphi[off] = __halves2half2(hx, hy);
                    *(half2*)&g_iplo[off] = __halves2half2(lx, ly);
                }
            }
}

/* ============ split+transpose weights: dst[c][r] = split(src[r][c]) ======= */
__global__ void split_trans_kernel(const float* __restrict__ src, int rows, int cols, int which)
{
    half* dh = which ? g_WinHi : g_Whi;
    half* dl = which ? g_WinLo : g_Wlo;
    __shared__ float t[32][33];
    int c0 = blockIdx.x * 32, r0 = blockIdx.y * 32;
    for (int j = threadIdx.y; j < 32; j += 8)
        t[j][threadIdx.x] = src[(size_t)(r0 + j) * cols + c0 + threadIdx.x];
    __syncthreads();
    for (int j = threadIdx.y; j < 32; j += 8) {
        float f = t[threadIdx.x][j];
        half h, l; split16(f, h, l);
        size_t o = (size_t)(c0 + j) * rows + r0 + threadIdx.x;
        dh[o] = h; dl[o] = l;
    }
}

/* ============ split input rows (no transpose) ============================= */
__global__ void split_input_kernel(const float* __restrict__ src)
{
    int idx = blockIdx.x * 256 + threadIdx.x;
    float f = src[idx];
    half h, l; split16(f, h, l);
    g_xhi[idx] = h; g_xlo[idx] = l;
}

/* =================== step s=0 (state was zero), half2-wide ================ */
__global__ __launch_bounds__(256) void init0_kernel()
{
    int idx = blockIdx.x * 256 + threadIdx.x;
    int row = idx >> 10, q2 = (idx & 1023) * 2;
    int b = row >> 7, w = row & 127;
    int t = 4 * w - 2;
    half2 ph = __float2half2_rn(0.f), pl = ph;
    if (t >= 0) {
        size_t uo = ((size_t)(b << 9) + t) * RES + q2;
        float2 u = rec2(*(const half2*)&g_iphi[uo], *(const half2*)&g_iplo[uo]);
        float vx = 0.3f * sinf(u.x), vy = 0.3f * sinf(u.y);
        half hx, lx, hy, ly;
        split16(vx, hx, lx); split16(vy, hy, ly);
        ph = __halves2half2(hx, hy); pl = __halves2half2(lx, ly);
    }
    size_t so = (size_t)row * RES + q2;
    *(half2*)&g_Shi0[so] = ph;
    *(half2*)&g_Slo0[so] = pl;
}

/* ====== transpose Cholesky factors: g_LT[b][j][i] = g_A[b][i][j] ========== */
__global__ void transL_kernel()
{
    const int b = blockIdx.z;
    const float* src = g_A + (size_t)b * TLEN * TLEN;
    float* dst = g_LT + (size_t)b * TLEN * TLEN;
    __shared__ float t[32][33];
    int c0 = blockIdx.x * 32, r0 = blockIdx.y * 32;
    for (int j = threadIdx.y; j < 32; j += 8)
        t[j][threadIdx.x] = src[(size_t)(r0 + j) * TLEN + c0 + threadIdx.x];
    __syncthreads();
    for (int j = threadIdx.y; j < 32; j += 8)
        dst[(size_t)(c0 + j) * TLEN + r0 + threadIdx.x] = t[threadIdx.x][j];
}

/* ============ blocked Cholesky, NB=64 (2 barriers/iter) =================== */
__global__ __launch_bounds__(256) void chol_panel_kernel(int p)
{
    const int b = blockIdx.x;
    float* Ab = g_A + (size_t)b * TLEN * TLEN;
    const int jb = p * 64;
    __shared__ float L11[64][65];
    __shared__ float diag[64];
    const int tid = threadIdx.x;
    for (int idx = tid; idx < 64 * 64; idx += 256) {
        int r = idx >> 6, c = idx & 63;
        L11[r][c] = Ab[(jb + r) * TLEN + jb + c];
    }
    __syncthreads();
    for (int k = 0; k < 64; k++) {
        /* phase 1: redundant sqrt in all threads (deterministic), divide col */
        float sq = sqrtf(L11[k][k]);
        if (tid == k) diag[k] = sq;
        if (tid > k && tid < 64) L11[tid][k] /= sq;
        __syncthreads();
        /* phase 2: rank-1 update of trailing lower triangle */
        for (int idx = tid; idx < 64 * 64; idx += 256) {
            int r = idx >> 6, c = idx & 63;
            if (r > k && c > k && c <= r) L11[r][c] -= L11[r][k] * L11[c][k];
        }
        __syncthreads();
    }
    for (int idx = tid; idx < 64 * 64; idx += 256) {
        int r = idx >> 6, c = idx & 63;
        if (c < r)       Ab[(jb + r) * TLEN + jb + c] = L11[r][c];
        else if (c == r) Ab[(jb + r) * TLEN + jb + c] = diag[r];
    }
    __syncthreads();
    const int mrows = TLEN - jb - 64;
    for (int r = tid; r < mrows; r += 256) {
        int i = jb + 64 + r;
        float a[64];
        #pragma unroll
        for (int c = 0; c < 64; c++) a[c] = Ab[i * TLEN + jb + c];
        #pragma unroll
        for (int k = 0; k < 64; k++) {
            float sv = a[k];
            #pragma unroll
            for (int q = 0; q < k; q++) sv -= a[q] * L11[k][q];
            a[k] = sv / diag[k];
        }
        #pragma unroll
        for (int c = 0; c < 64; c++) Ab[i * TLEN + jb + c] = a[c];
    }
}

__global__ __launch_bounds__(256) void chol_update_kernel(int p)
{
    const int jb = p * 64 + 64;
    int idx = blockIdx.x;
    int ti = 0;
    while ((ti + 1) * (ti + 2) / 2 <= idx) ti++;
    int tj = idx - ti * (ti + 1) / 2;
    const int b = blockIdx.y;
    float* Ab = g_A + (size_t)b * TLEN * TLEN;
    const int r0 = jb + ti * 64, c0 = jb + tj * 64;
    __shared__ float La[64][65], Lb[64][65];
    const int tid = threadIdx.x;
    for (int q = tid; q < 64 * 64; q += 256) {
        int r = q >> 6, c = q & 63;
        La[r][c] = Ab[(r0 + r) * TLEN + p * 64 + c];
        Lb[r][c] = Ab[(c0 + r) * TLEN + p * 64 + c];
    }
    __syncthreads();
    const int tx = tid & 15, ty = tid >> 4;
    float acc[4][4] = {};
    #pragma unroll
    for (int k = 0; k < 64; k++) {
        float ar[4], bc[4];
        #pragma unroll
        for (int i = 0; i < 4; i++) ar[i] = La[ty * 4 + i][k];
        #pragma unroll
        for (int j = 0; j < 4; j++) bc[j] = Lb[tx * 4 + j][k];
        #pragma unroll
        for (int i = 0; i < 4; i++)
            #pragma unroll
            for (int j = 0; j < 4; j++)
                acc[i][j] += ar[i] * bc[j];
    }
    #pragma unroll
    for (int i = 0; i < 4; i++)
        #pragma unroll
        for (int j = 0; j < 4; j++)
            Ab[(r0 + ty * 4 + i) * TLEN + c0 + tx * 4 + j] -= acc[i][j];
}

/* ============ blocked triangular solves, 64 RHS in registers ==============
   8 diagonal blocks of 64; within-block solve uses 2-warp named barriers,
   trailing updates run barrier-free in bulk. Same per-element summation
   order as the sequential version -> bit-identical results.               */
__global__ __launch_bounds__(512) void solve_kernel(const float* __restrict__ Y)
{
    const int b = blockIdx.x;
    const int i = threadIdx.x;
    const float* __restrict__ Ab = g_A + (size_t)b * TLEN * TLEN;
    const float* __restrict__ Lt = g_LT + (size_t)b * TLEN * TLEN;
    float acc[OUTD];
    #pragma unroll
    for (int o = 0; o < OUTD; o++) acc[o] = Y[((size_t)b * TLEN + i) * OUTD + o];
    __shared__ float zs[64][65];

    /* ---------------- forward: L w = y ---------------- */
    for (int jb = 0; jb < 8; jb++) {
        const int base = jb * 64;
        __syncthreads();                     /* zs free for reuse */
        if (i >= base && i < base + 64) {
            const int kl = i - base;
            for (int k = 0; k < 64; k++) {
                if (kl == k) {
                    float dinv = 1.f / Ab[i * TLEN + i];
                    #pragma unroll
                    for (int o = 0; o < OUTD; o++) { acc[o] *= dinv; zs[k][o] = acc[o]; }
                }
                asm volatile("bar.sync 1, 64;" ::: "memory");
                if (kl > k) {
                    float lij = Lt[(base + k) * TLEN + i];
                    #pragma unroll
                    for (int o = 0; o < OUTD; o++) acc[o] -= lij * zs[k][o];
                }
            }
        }
        __syncthreads();                     /* zs complete, visible to all */
        if (i >= base + 64) {
            #pragma unroll 2
            for (int k = 0; k < 64; k++) {
                float lij = Lt[(base + k) * TLEN + i];
                #pragma unroll
                for (int o = 0; o < OUTD; o++) acc[o] -= lij * zs[k][o];
            }
        }
    }

    /* ---------------- backward: L^T z = w ---------------- */
    for (int jb = 7; jb >= 0; jb--) {
        const int base = jb * 64;
        __syncthreads();
        if (i >= base && i < base + 64) {
            const int kl = i - base;
            for (int k = 63; k >= 0; k--) {
                if (kl == k) {
                    float dinv = 1.f / Ab[i * TLEN + i];
                    #pragma unroll
                    for (int o = 0; o < OUTD; o++) { acc[o] *= dinv; zs[k][o] = acc[o]; }
                }
                asm volatile("bar.sync 1, 64;" ::: "memory");
                if (kl < k) {
                    float lji = Ab[(base + k) * TLEN + i];
                    #pragma unroll
                    for (int o = 0; o < OUTD; o++) acc[o] -= lji * zs[k][o];
                }
            }
        }
        __syncthreads();
        if (i < base) {
            #pragma unroll 2
            for (int k = 63; k >= 0; k--) {
                float lji = Ab[(base + k) * TLEN + i];
                #pragma unroll
                for (int o = 0; o < OUTD; o++) acc[o] -= lji * zs[k][o];
            }
        }
    }
    #pragma unroll
    for (int o = 0; o < OUTD; o++) g_Z[((size_t)b * TLEN + i) * OUTD + o] = acc[o];
}

/* ============ W = Xb^T Z  (2048 x 64, K=512), X from rs planes ============ */
__global__ __launch_bounds__(256) void wout_kernel(float* __restrict__ out)
{
    const int b = blockIdx.y;
    const half* __restrict__ Xh = g_rshi + (size_t)b * TLEN * RES;
    const half* __restrict__ Xl = g_rslo + (size_t)b * TLEN * RES;
    const float* __restrict__ Zb = g_Z + (size_t)b * TLEN * OUTD;
    const int d0 = blockIdx.x * 128;
    __shared__ float As2[16][132];
    __shared__ float Bs2[16][68];
    const int tid = threadIdx.x;
    const int lr = tid >> 4, lc = (tid & 15) * 4;
    const int ty = tid >> 4, tx = tid & 15;
    float acc[8][4] = {};
    for (int k0 = 0; k0 < TLEN; k0 += 16) {
        #pragma unroll
        for (int half64 = 0; half64 < 2; half64++) {
            size_t off = (size_t)(k0 + lr) * RES + d0 + lc + half64 * 64;
            half2 h0 = *(const half2*)&Xh[off],     h1 = *(const half2*)&Xh[off + 2];
            half2 l0 = *(const half2*)&Xl[off],     l1 = *(const half2*)&Xl[off + 2];
            float2 a0 = rec2(h0, l0), a1 = rec2(h1, l1);
            As2[lr][lc + half64 * 64 + 0] = a0.x;
            As2[lr][lc + half64 * 64 + 1] = a0.y;
            As2[lr][lc + half64 * 64 + 2] = a1.x;
            As2[lr][lc + half64 * 64 + 3] = a1.y;
        }
        *(float4*)&Bs2[lr][lc] = *(const float4*)&Zb[(k0 + lr) * OUTD + lc];
        __syncthreads();
        #pragma unroll
        for (int k = 0; k < 16; k++) {
            float fa[8], fb[4];
            *(float4*)&fa[0] = *(const float4*)&As2[k][ty * 8];
            *(float4*)&fa[4] = *(const float4*)&As2[k][ty * 8 + 4];
            *(float4*)&fb[0] = *(const float4*)&Bs2[k][tx * 4];
            #pragma unroll
            for (int i = 0; i < 8; i++)
                #pragma unroll
                for (int j = 0; j < 4; j++)
                    acc[i][j] += fa[i] * fb[j];
        }
        __syncthreads();
    }
    #pragma unroll
    for (int i = 0; i < 8; i++)
        #pragma unroll
        for (int j = 0; j < 4; j++)
            out[((size_t)b * RES + d0 + ty * 8 + i) * OUTD + tx * 4 + j] = acc[i][j];
}

__global__ void bias_kernel(float* __restrict__ out)
{
    const int b = blockIdx.x, o = threadIdx.x;
    float s = 0.f;
    for (int n = 0; n < TLEN; n++) s += g_Z[((size_t)b * TLEN + n) * OUTD + o];
    out[(size_t)BATCH * RES * OUTD + b * OUTD + o] = s;
}

/* ======================= launch ======================= */
extern "C" void kernel_launch(void* const* d_in, const int* in_sizes, int n_in,
                              void* d_out, int out_size)
{
    const float* input  = (const float*)d_in[0];
    const float* target = (const float*)d_in[1];
    const float* W_res  = (const float*)d_in[2];
    const float* W_in   = (const float*)d_in[3];
    const float* lam    = (const float*)d_in[4];
    float* out = (float*)d_out;

    cudaFuncSetAttribute(tc_kernel, cudaFuncAttributeMaxDynamicSharedMemorySize, SMEM_DYN);

    /* 0. split+transpose weights, split input */
    split_trans_kernel<<<dim3(RES / 32, RES / 32), dim3(32, 8)>>>(W_res, RES, RES, 0);
    split_trans_kernel<<<dim3(RES / 32, INDIM / 32), dim3(32, 8)>>>(W_in, INDIM, RES, 1);
    split_input_kernel<<<(NROWS * INDIM) / 256, 256>>>(input);

    /* 1. input projection (writes inproj planes) */
    tc_kernel<<<dim3(RES / 128, NROWS / 128), 256, SMEM_DYN>>>(2, 0, 0, nullptr);

    /* 2. reservoir (state lives only as hi/lo planes) */
    init0_kernel<<<(MROWS * RES / 2) / 256, 256>>>();
    int flip = 0;
    for (int s = 1; s <= 5; s++) {
        tc_kernel<<<dim3(RES / 128, MROWS / 128), 256, SMEM_DYN>>>(0, s, flip, nullptr);
        flip ^= 1;
    }

    /* 3. gram: 10 lower (128x128) tiles; upper triangle never read */
    tc_kernel<<<dim3(10, 1, BATCH), 256, SMEM_DYN>>>(1, 0, 0, lam);

    /* 4. batched blocked Cholesky */
    for (int p = 0; p < 8; p++) {
        chol_panel_kernel<<<BATCH, 256>>>(p);
        if (p < 7) {
            int mt = 7 - p;
            chol_update_kernel<<<dim3(mt * (mt + 1) / 2, BATCH), 256>>>(p);
        }
    }

    /* 4b. transpose L for coalesced forward solve */
    transL_kernel<<<dim3(16, 16, BATCH), dim3(32, 8)>>>();

    /* 5. blocked triangular solves */
    solve_kernel<<<BATCH, 512>>>(target);

    /* 6. readout */
    wout_kernel<<<dim3(RES / 128, BATCH), 256>>>(out);
    bias_kernel<<<BATCH, 64>>>(out);

    (void)in_sizes; (void)n_in; (void)out_size;
}

// round 12
// speedup vs baseline: 1.1860x; 1.1860x over previous
#include <cuda_runtime.h>
#include <cuda_fp16.h>
#include <math.h>
#include <stdint.h>

#define BATCH 32
#define TLEN  512
#define INDIM 128
#define RES   2048
#define OUTD  64
#define NWIN  128
#define MROWS (BATCH*NWIN)   /* 4096  reservoir rows (b,w) */
#define NROWS (BATCH*TLEN)   /* 16384 time rows (b,t)      */

/* ---------------- scratch (device globals; no allocations) ---------------- */
__device__ float g_A[BATCH * TLEN * TLEN]; /* gram matrices          32 MB */
__device__ float g_LT[BATCH * TLEN * TLEN];/* L transposed           32 MB */
__device__ float g_Z[BATCH * TLEN * OUTD]; /* solve result            4 MB */
/* fp16 split planes (hi+lo reconstructs fp32 to ~2^-22) */
__device__ half g_Shi0[MROWS * RES], g_Slo0[MROWS * RES];   /* state ping */
__device__ half g_Shi1[MROWS * RES], g_Slo1[MROWS * RES];   /* state pong */
__device__ half g_rshi[NROWS * RES], g_rslo[NROWS * RES];   /* rs states  */
__device__ half g_iphi[NROWS * RES], g_iplo[NROWS * RES];   /* inproj     */
__device__ half g_Whi[RES * RES],   g_Wlo[RES * RES];       /* WresT      */
__device__ half g_WinHi[RES * INDIM], g_WinLo[RES * INDIM]; /* WinT       */
__device__ half g_xhi[NROWS * INDIM], g_xlo[NROWS * INDIM]; /* input      */

/* ====================== helpers ====================== */
__device__ __forceinline__ uint32_t smem_u32(const void* p) {
    uint32_t a;
    asm("{ .reg .u64 t; cvta.to.shared.u64 t, %1; cvt.u32.u64 %0, t; }" : "=r"(a) : "l"(p));
    return a;
}
__device__ __forceinline__ void cpasync16(uint32_t dst, const void* src) {
    asm volatile("cp.async.cg.shared.global [%0], [%1], 16;" :: "r"(dst), "l"(src));
}
__device__ __forceinline__ void cp_commit() { asm volatile("cp.async.commit_group;" ::: "memory"); }
__device__ __forceinline__ void cp_wait1()  { asm volatile("cp.async.wait_group 1;" ::: "memory"); }
__device__ __forceinline__ void cp_wait0()  { asm volatile("cp.async.wait_group 0;" ::: "memory"); }

__device__ __forceinline__ void ldsm4(uint32_t* r, uint32_t addr) {
    asm volatile("ldmatrix.sync.aligned.m8n8.x4.shared.b16 {%0,%1,%2,%3}, [%4];"
        : "=r"(r[0]), "=r"(r[1]), "=r"(r[2]), "=r"(r[3]) : "r"(addr));
}
__device__ __forceinline__ void mma16816(float* d, const uint32_t* a, uint32_t b0, uint32_t b1) {
    asm volatile(
        "mma.sync.aligned.m16n8k16.row.col.f32.f16.f16.f32 "
        "{%0,%1,%2,%3},{%4,%5,%6,%7},{%8,%9},{%0,%1,%2,%3};"
        : "+f"(d[0]), "+f"(d[1]), "+f"(d[2]), "+f"(d[3])
        : "r"(a[0]), "r"(a[1]), "r"(a[2]), "r"(a[3]), "r"(b0), "r"(b1));
}
__device__ __forceinline__ void split16(float f, half& h, half& l) {
    h = __float2half_rn(f);
    l = __float2half_rn(f - __half2float(h));
}
__device__ __forceinline__ float2 rec2(half2 h, half2 l) {
    float2 fh = __half22float2(h), fl = __half22float2(l);
    return make_float2(fh.x + fl.x, fh.y + fl.y);
}

/* ============ fp16x3 GEMM kernel (mma.sync m16n8k16) ====================== */
#define A_PLANE 8192
#define B_PLANE 8192
#define STAGE_B 32768
#define SMEM_DYN (3*STAGE_B)   /* 98304 */

__global__ __launch_bounds__(256, 2) void tc_kernel(
    int mode, int s, int flip, const float* __restrict__ lam)
{
    extern __shared__ char smem[];
    const uint32_t smem_u = smem_u32(smem);

    const int tid = threadIdx.x;
    const int wid = tid >> 5, lane = tid & 31;
    const int gid = lane >> 2, tig = lane & 3;
    const int m = lane >> 3, l7 = lane & 7;
    const int warpM = wid >> 2, warpN = wid & 3;
    const int rowBase = warpM * 64, colBase = warpN * 32;

    int row0, col0;
    if (mode == 1) {
        int x = blockIdx.x, ti = 0;
        while ((ti + 1) * (ti + 2) / 2 <= x) ti++;
        int tj = x - ti * (ti + 1) / 2;
        row0 = ti * 128; col0 = tj * 128;
    } else {
        row0 = blockIdx.y * 128; col0 = blockIdx.x * 128;
    }

    const half *Ahi, *Alo, *Bhi, *Blo; int K;
    if (mode == 0) {
        Ahi = flip ? g_Shi1 : g_Shi0; Alo = flip ? g_Slo1 : g_Slo0;
        Bhi = g_Whi; Blo = g_Wlo; K = RES;
    } else if (mode == 1) {
        size_t base = (size_t)blockIdx.z * TLEN * RES;
        Ahi = g_rshi + base; Alo = g_rslo + base;
        Bhi = Ahi; Blo = Alo; K = RES;
    } else {
        Ahi = g_xhi; Alo = g_xlo; Bhi = g_WinHi; Blo = g_WinLo; K = INDIM;
    }
    const int nIter = K >> 5;

    float acc[4][4][4] = {};

    uint32_t aRB[4], aX[4], bRB[2], bX[2];
    #pragma unroll
    for (int mt = 0; mt < 4; mt++) {
        uint32_t r = rowBase + mt * 16 + (m & 1) * 8 + l7;
        aRB[mt] = r * 64; aX[mt] = (r >> 1) & 3;
    }
    #pragma unroll
    for (int np = 0; np < 2; np++) {
        uint32_t n = colBase + (np * 2 + (m >> 1)) * 8 + l7;
        bRB[np] = n * 64; bX[np] = (n >> 1) & 3;
    }
    const uint32_t amk = (uint32_t)(m >> 1);
    const uint32_t bmk = (uint32_t)(m & 1);

    auto load_chunk = [&](int it, int stage) {
        const int k0 = it << 5;
        const uint32_t sb = smem_u + (uint32_t)stage * STAGE_B;
        #pragma unroll
        for (int q = 0; q < 8; q++) {
            int idx = tid + q * 256;
            int op = idx >> 10;
            int j = idx & 1023;
            int p = j >> 9, r = (j >> 2) & 127, c = j & 3;
            const half* gp = op ? (p ? Blo : Bhi) : (p ? Alo : Ahi);
            int rowg = (op ? col0 : row0) + r;
            const half* src = gp + (size_t)rowg * K + k0 + c * 8;
            uint32_t dst = sb + (uint32_t)op * (2 * A_PLANE) + (uint32_t)p * A_PLANE
                         + (uint32_t)r * 64 + (uint32_t)((c ^ ((r >> 1) & 3)) * 16);
            cpasync16(dst, src);
        }
    };

    load_chunk(0, 0);
    cp_commit();
    if (nIter > 1) { load_chunk(1, 1); cp_commit(); }

    for (int it = 0; it < nIter; ++it) {
        if (it + 1 < nIter) cp_wait1(); else cp_wait0();
        __syncthreads();
        if (it + 2 < nIter) { load_chunk(it + 2, (it + 2) % 3); cp_commit(); }

        const uint32_t sb = smem_u + (uint32_t)(it % 3) * STAGE_B;
        const uint32_t pAh = sb, pAl = sb + A_PLANE;
        const uint32_t pBh = sb + 2 * A_PLANE, pBl = pBh + B_PLANE;
        #pragma unroll
        for (int h16 = 0; h16 < 2; h16++) {
            uint32_t bh[2][4], bl[2][4];
            #pragma unroll
            for (int np = 0; np < 2; np++) {
                uint32_t off = bRB[np] + (((h16 * 2 + bmk) ^ bX[np]) * 16);
                ldsm4(bh[np], pBh + off);
                ldsm4(bl[np], pBl + off);
            }
            #pragma unroll
            for (int mt = 0; mt < 4; mt++) {
                uint32_t ah[4], al[4];
                uint32_t off = aRB[mt] + (((h16 * 2 + amk) ^ aX[mt]) * 16);
                ldsm4(ah, pAh + off);
                ldsm4(al, pAl + off);
                #pragma unroll
                for (int nt = 0; nt < 4; nt++) {
                    uint32_t b0h = bh[nt >> 1][(nt & 1) * 2], b1h = bh[nt >> 1][(nt & 1) * 2 + 1];
                    uint32_t b0l = bl[nt >> 1][(nt & 1) * 2], b1l = bl[nt >> 1][(nt & 1) * 2 + 1];
                    mma16816(acc[mt][nt], ah, b0h, b1h);
                    mma16816(acc[mt][nt], ah, b0l, b1l);
                    mma16816(acc[mt][nt], al, b0h, b1h);
                }
            }
        }
    }

    /* -------------------- epilogue (register -> global, planes only) ------- */
    float regc = 0.f;
    if (mode == 1) { float l = lam[0]; regc = log1pf(expf(l)); }
    const half* SoHi = flip ? g_Shi1 : g_Shi0;
    const half* SoLo = flip ? g_Slo1 : g_Slo0;
    half* ShiN = flip ? g_Shi0 : g_Shi1;
    half* SloN = flip ? g_Slo0 : g_Slo1;

    #pragma unroll
    for (int mt = 0; mt < 4; mt++)
        #pragma unroll
        for (int nt = 0; nt < 4; nt++)
            #pragma unroll
            for (int h = 0; h < 2; h++) {
                int grow = row0 + rowBase + mt * 16 + gid + h * 8;
                int col = col0 + colBase + nt * 8 + tig * 2;
                float cx = acc[mt][nt][h * 2 + 0];
                float cy = acc[mt][nt][h * 2 + 1];
                if (mode == 0) {
                    int b = grow >> 7, w = grow & 127;
                    int t = 4 * w + s - 2;
                    size_t so_off = (size_t)grow * RES + col;
                    float2 so = rec2(*(const half2*)&SoHi[so_off],
                                     *(const half2*)&SoLo[so_off]);
                    float2 u = make_float2(0.f, 0.f);
                    if (t >= 0) {
                        size_t uo = ((size_t)(b << 9) + t) * RES + col;
                        u = rec2(*(const half2*)&g_iphi[uo], *(const half2*)&g_iplo[uo]);
                    }
                    float2 v;
                    v.x = 0.7f * so.x + 0.3f * sinf(cx + u.x);
                    v.y = 0.7f * so.y + 0.3f * sinf(cy + u.y);
                    half hx, lx, hy, ly;
                    split16(v.x, hx, lx); split16(v.y, hy, ly);
                    *(half2*)&ShiN[so_off] = __halves2half2(hx, hy);
                    *(half2*)&SloN[so_off] = __halves2half2(lx, ly);
                    if (s >= 2) {
                        size_t ro = ((size_t)(b << 9) + t) * RES + col;
                        *(half2*)&g_rshi[ro] = __halves2half2(hx, hy);
                        *(half2*)&g_rslo[ro] = __halves2half2(lx, ly);
                    }
                } else if (mode == 1) {
                    float* Abm = g_A + (size_t)blockIdx.z * TLEN * TLEN;
                    float2 v;
                    v.x = cx + 1.0f + ((grow == col + 0) ? regc : 0.f);
                    v.y = cy + 1.0f + ((grow == col + 1) ? regc : 0.f);
                    *(float2*)&Abm[(size_t)grow * TLEN + col] = v;
                } else {
                    half hx, lx, hy, ly;
                    split16(cx, hx, lx); split16(cy, hy, ly);
                    size_t off = (size_t)grow * RES + col;
                    *(half2*)&g_iphi[off] = __halves2half2(hx, hy);
                    *(half2*)&g_iplo[off] = __halves2half2(lx, ly);
                }
            }
}

/* ============ split+transpose weights: dst[c][r] = split(src[r][c]) ======= */
__global__ void split_trans_kernel(const float* __restrict__ src, int rows, int cols, int which)
{
    half* dh = which ? g_WinHi : g_Whi;
    half* dl = which ? g_WinLo : g_Wlo;
    __shared__ float t[32][33];
    int c0 = blockIdx.x * 32, r0 = blockIdx.y * 32;
    for (int j = threadIdx.y; j < 32; j += 8)
        t[j][threadIdx.x] = src[(size_t)(r0 + j) * cols + c0 + threadIdx.x];
    __syncthreads();
    for (int j = threadIdx.y; j < 32; j += 8) {
        float f = t[threadIdx.x][j];
        half h, l; split16(f, h, l);
        size_t o = (size_t)(c0 + j) * rows + r0 + threadIdx.x;
        dh[o] = h; dl[o] = l;
    }
}

/* ============ split input rows (no transpose) ============================= */
__global__ void split_input_kernel(const float* __restrict__ src)
{
    int idx = blockIdx.x * 256 + threadIdx.x;
    float f = src[idx];
    half h, l; split16(f, h, l);
    g_xhi[idx] = h; g_xlo[idx] = l;
}

/* =================== step s=0 (state was zero), half2-wide ================ */
__global__ __launch_bounds__(256) void init0_kernel()
{
    int idx = blockIdx.x * 256 + threadIdx.x;
    int row = idx >> 10, q2 = (idx & 1023) * 2;
    int b = row >> 7, w = row & 127;
    int t = 4 * w - 2;
    half2 ph = __float2half2_rn(0.f), pl = ph;
    if (t >= 0) {
        size_t uo = ((size_t)(b << 9) + t) * RES + q2;
        float2 u = rec2(*(const half2*)&g_iphi[uo], *(const half2*)&g_iplo[uo]);
        float vx = 0.3f * sinf(u.x), vy = 0.3f * sinf(u.y);
        half hx, lx, hy, ly;
        split16(vx, hx, lx); split16(vy, hy, ly);
        ph = __halves2half2(hx, hy); pl = __halves2half2(lx, ly);
    }
    size_t so = (size_t)row * RES + q2;
    *(half2*)&g_Shi0[so] = ph;
    *(half2*)&g_Slo0[so] = pl;
}

/* ====== transpose Cholesky factors (only blocks the solve reads) ========== */
__global__ void transL_kernel()
{
    const int b = blockIdx.z;
    int c0 = blockIdx.x * 32, r0 = blockIdx.y * 32;
    /* forward solve reads Lt[j][i] only for i > j: dst row=c0+j, col=r0+tx.
       Block entirely dead when every col <= every row: c0 > r0 + 31.        */
    if (c0 > r0 + 31) return;
    const float* src = g_A + (size_t)b * TLEN * TLEN;
    float* dst = g_LT + (size_t)b * TLEN * TLEN;
    __shared__ float t[32][33];
    for (int j = threadIdx.y; j < 32; j += 8)
        t[j][threadIdx.x] = src[(size_t)(r0 + j) * TLEN + c0 + threadIdx.x];
    __syncthreads();
    for (int j = threadIdx.y; j < 32; j += 8)
        dst[(size_t)(c0 + j) * TLEN + r0 + threadIdx.x] = t[threadIdx.x][j];
}

/* ============ blocked Cholesky, NB=64 (2 barriers/iter) =================== */
__global__ __launch_bounds__(256) void chol_panel_kernel(int p)
{
    const int b = blockIdx.x;
    float* Ab = g_A + (size_t)b * TLEN * TLEN;
    const int jb = p * 64;
    __shared__ float L11[64][65];
    __shared__ float diag[64];
    const int tid = threadIdx.x;
    for (int idx = tid; idx < 64 * 64; idx += 256) {
        int r = idx >> 6, c = idx & 63;
        L11[r][c] = Ab[(jb + r) * TLEN + jb + c];
    }
    __syncthreads();
    for (int k = 0; k < 64; k++) {
        /* redundant sqrt in all threads (deterministic); write via diag[] */
        float sq = sqrtf(L11[k][k]);
        if (tid == k) diag[k] = sq;
        if (tid > k && tid < 64) L11[tid][k] /= sq;
        __syncthreads();
        for (int idx = tid; idx < 64 * 64; idx += 256) {
            int r = idx >> 6, c = idx & 63;
            if (r > k && c > k && c <= r) L11[r][c] -= L11[r][k] * L11[c][k];
        }
        __syncthreads();
    }
    for (int idx = tid; idx < 64 * 64; idx += 256) {
        int r = idx >> 6, c = idx & 63;
        if (c < r)       Ab[(jb + r) * TLEN + jb + c] = L11[r][c];
        else if (c == r) Ab[(jb + r) * TLEN + jb + c] = diag[r];
    }
    __syncthreads();
    const int mrows = TLEN - jb - 64;
    for (int r = tid; r < mrows; r += 256) {
        int i = jb + 64 + r;
        float a[64];
        #pragma unroll
        for (int c = 0; c < 64; c++) a[c] = Ab[i * TLEN + jb + c];
        #pragma unroll
        for (int k = 0; k < 64; k++) {
            float sv = a[k];
            #pragma unroll
            for (int q = 0; q < k; q++) sv -= a[q] * L11[k][q];
            a[k] = sv / diag[k];
        }
        #pragma unroll
        for (int c = 0; c < 64; c++) Ab[i * TLEN + jb + c] = a[c];
    }
}

__global__ __launch_bounds__(256) void chol_update_kernel(int p)
{
    const int jb = p * 64 + 64;
    int idx = blockIdx.x;
    int ti = 0;
    while ((ti + 1) * (ti + 2) / 2 <= idx) ti++;
    int tj = idx - ti * (ti + 1) / 2;
    const int b = blockIdx.y;
    float* Ab = g_A + (size_t)b * TLEN * TLEN;
    const int r0 = jb + ti * 64, c0 = jb + tj * 64;
    __shared__ float La[64][65], Lb[64][65];
    const int tid = threadIdx.x;
    for (int q = tid; q < 64 * 64; q += 256) {
        int r = q >> 6, c = q & 63;
        La[r][c] = Ab[(r0 + r) * TLEN + p * 64 + c];
        Lb[r][c] = Ab[(c0 + r) * TLEN + p * 64 + c];
    }
    __syncthreads();
    const int tx = tid & 15, ty = tid >> 4;
    float acc[4][4] = {};
    #pragma unroll
    for (int k = 0; k < 64; k++) {
        float ar[4], bc[4];
        #pragma unroll
        for (int i = 0; i < 4; i++) ar[i] = La[ty * 4 + i][k];
        #pragma unroll
        for (int j = 0; j < 4; j++) bc[j] = Lb[tx * 4 + j][k];
        #pragma unroll
        for (int i = 0; i < 4; i++)
            #pragma unroll
            for (int j = 0; j < 4; j++)
                acc[i][j] += ar[i] * bc[j];
    }
    #pragma unroll
    for (int i = 0; i < 4; i++)
        #pragma unroll
        for (int j = 0; j < 4; j++)
            Ab[(r0 + ty * 4 + i) * TLEN + c0 + tx * 4 + j] -= acc[i][j];
}

/* ============ triangular solves, 64 RHS in registers (round-10 form) ====== */
__global__ __launch_bounds__(512) void solve_kernel(const float* __restrict__ Y)
{
    const int b = blockIdx.x;
    const int i = threadIdx.x;
    const float* __restrict__ Ab = g_A + (size_t)b * TLEN * TLEN;
    const float* __restrict__ Lt = g_LT + (size_t)b * TLEN * TLEN;
    float acc[OUTD];
    #pragma unroll
    for (int o = 0; o < OUTD; o++) acc[o] = Y[((size_t)b * TLEN + i) * OUTD + o];
    __shared__ float zrow[OUTD];
    for (int j = 0; j < TLEN; j++) {
        if (i == j) {
            float dinv = 1.f / Ab[j * TLEN + j];
            #pragma unroll
            for (int o = 0; o < OUTD; o++) { acc[o] *= dinv; zrow[o] = acc[o]; }
        }
        __syncthreads();
        if (i > j) {
            float lij = Lt[j * TLEN + i];
            #pragma unroll
            for (int o = 0; o < OUTD; o++) acc[o] -= lij * zrow[o];
        }
        __syncthreads();
    }
    for (int j = TLEN - 1; j >= 0; j--) {
        if (i == j) {
            float dinv = 1.f / Ab[j * TLEN + j];
            #pragma unroll
            for (int o = 0; o < OUTD; o++) { acc[o] *= dinv; zrow[o] = acc[o]; }
        }
        __syncthreads();
        if (i < j) {
            float lji = Ab[j * TLEN + i];
            #pragma unroll
            for (int o = 0; o < OUTD; o++) acc[o] -= lji * zrow[o];
        }
        __syncthreads();
    }
    #pragma unroll
    for (int o = 0; o < OUTD; o++) g_Z[((size_t)b * TLEN + i) * OUTD + o] = acc[o];
}

/* ============ W = Xb^T Z  (2048 x 64, K=512), X from rs planes ============ */
__global__ __launch_bounds__(256) void wout_kernel(float* __restrict__ out)
{
    const int b = blockIdx.y;
    const half* __restrict__ Xh = g_rshi + (size_t)b * TLEN * RES;
    const half* __restrict__ Xl = g_rslo + (size_t)b * TLEN * RES;
    const float* __restrict__ Zb = g_Z + (size_t)b * TLEN * OUTD;
    const int d0 = blockIdx.x * 128;
    __shared__ float As2[16][132];
    __shared__ float Bs2[16][68];
    const int tid = threadIdx.x;
    const int lr = tid >> 4, lc = (tid & 15) * 4;
    const int ty = tid >> 4, tx = tid & 15;
    float acc[8][4] = {};
    for (int k0 = 0; k0 < TLEN; k0 += 16) {
        #pragma unroll
        for (int half64 = 0; half64 < 2; half64++) {
            size_t off = (size_t)(k0 + lr) * RES + d0 + lc + half64 * 64;
            half2 h0 = *(const half2*)&Xh[off],     h1 = *(const half2*)&Xh[off + 2];
            half2 l0 = *(const half2*)&Xl[off],     l1 = *(const half2*)&Xl[off + 2];
            float2 a0 = rec2(h0, l0), a1 = rec2(h1, l1);
            As2[lr][lc + half64 * 64 + 0] = a0.x;
            As2[lr][lc + half64 * 64 + 1] = a0.y;
            As2[lr][lc + half64 * 64 + 2] = a1.x;
            As2[lr][lc + half64 * 64 + 3] = a1.y;
        }
        *(float4*)&Bs2[lr][lc] = *(const float4*)&Zb[(k0 + lr) * OUTD + lc];
        __syncthreads();
        #pragma unroll
        for (int k = 0; k < 16; k++) {
            float fa[8], fb[4];
            *(float4*)&fa[0] = *(const float4*)&As2[k][ty * 8];
            *(float4*)&fa[4] = *(const float4*)&As2[k][ty * 8 + 4];
            *(float4*)&fb[0] = *(const float4*)&Bs2[k][tx * 4];
            #pragma unroll
            for (int i = 0; i < 8; i++)
                #pragma unroll
                for (int j = 0; j < 4; j++)
                    acc[i][j] += fa[i] * fb[j];
        }
        __syncthreads();
    }
    #pragma unroll
    for (int i = 0; i < 8; i++)
        #pragma unroll
        for (int j = 0; j < 4; j++)
            out[((size_t)b * RES + d0 + ty * 8 + i) * OUTD + tx * 4 + j] = acc[i][j];
}

__global__ void bias_kernel(float* __restrict__ out)
{
    const int b = blockIdx.x, o = threadIdx.x;
    float s = 0.f;
    for (int n = 0; n < TLEN; n++) s += g_Z[((size_t)b * TLEN + n) * OUTD + o];
    out[(size_t)BATCH * RES * OUTD + b * OUTD + o] = s;
}

/* ======================= launch ======================= */
extern "C" void kernel_launch(void* const* d_in, const int* in_sizes, int n_in,
                              void* d_out, int out_size)
{
    const float* input  = (const float*)d_in[0];
    const float* target = (const float*)d_in[1];
    const float* W_res  = (const float*)d_in[2];
    const float* W_in   = (const float*)d_in[3];
    const float* lam    = (const float*)d_in[4];
    float* out = (float*)d_out;

    cudaFuncSetAttribute(tc_kernel, cudaFuncAttributeMaxDynamicSharedMemorySize, SMEM_DYN);

    /* 0. split+transpose weights, split input */
    split_trans_kernel<<<dim3(RES / 32, RES / 32), dim3(32, 8)>>>(W_res, RES, RES, 0);
    split_trans_kernel<<<dim3(RES / 32, INDIM / 32), dim3(32, 8)>>>(W_in, INDIM, RES, 1);
    split_input_kernel<<<(NROWS * INDIM) / 256, 256>>>(input);

    /* 1. input projection (writes inproj planes) */
    tc_kernel<<<dim3(RES / 128, NROWS / 128), 256, SMEM_DYN>>>(2, 0, 0, nullptr);

    /* 2. reservoir (state lives only as hi/lo planes) */
    init0_kernel<<<(MROWS * RES / 2) / 256, 256>>>();
    int flip = 0;
    for (int s = 1; s <= 5; s++) {
        tc_kernel<<<dim3(RES / 128, MROWS / 128), 256, SMEM_DYN>>>(0, s, flip, nullptr);
        flip ^= 1;
    }

    /* 3. gram: 10 lower (128x128) tiles; upper triangle never read */
    tc_kernel<<<dim3(10, 1, BATCH), 256, SMEM_DYN>>>(1, 0, 0, lam);

    /* 4. batched blocked Cholesky */
    for (int p = 0; p < 8; p++) {
        chol_panel_kernel<<<BATCH, 256>>>(p);
        if (p < 7) {
            int mt = 7 - p;
            chol_update_kernel<<<dim3(mt * (mt + 1) / 2, BATCH), 256>>>(p);
        }
    }

    /* 4b. transpose L (live blocks only) for coalesced forward solve */
    transL_kernel<<<dim3(16, 16, BATCH), dim3(32, 8)>>>();

    /* 5. triangular solves */
    solve_kernel<<<BATCH, 512>>>(target);

    /* 6. readout */
    wout_kernel<<<dim3(RES / 128, BATCH), 256>>>(out);
    bias_kernel<<<BATCH, 64>>>(out);

    (void)in_sizes; (void)n_in; (void)out_size;
}

// round 13
// speedup vs baseline: 1.2330x; 1.0396x over previous
#include <cuda_runtime.h>
#include <cuda_fp16.h>
#include <math.h>
#include <stdint.h>

#define BATCH 32
#define TLEN  512
#define INDIM 128
#define RES   2048
#define OUTD  64
#define NWIN  128
#define MROWS (BATCH*NWIN)   /* 4096  reservoir rows (b,w) */
#define NROWS (BATCH*TLEN)   /* 16384 time rows (b,t)      */

/* ---------------- scratch (device globals; no allocations) ---------------- */
__device__ float g_A[BATCH * TLEN * TLEN]; /* gram matrices          32 MB */
__device__ float g_LT[BATCH * TLEN * TLEN];/* L transposed           32 MB */
__device__ float g_Z[BATCH * TLEN * OUTD]; /* solve result            4 MB */
/* fp16 split planes (hi+lo reconstructs fp32 to ~2^-22) */
__device__ half g_Shi0[MROWS * RES], g_Slo0[MROWS * RES];   /* state ping */
__device__ half g_Shi1[MROWS * RES], g_Slo1[MROWS * RES];   /* state pong */
__device__ half g_rshi[NROWS * RES], g_rslo[NROWS * RES];   /* rs states  */
__device__ half g_iphi[NROWS * RES], g_iplo[NROWS * RES];   /* inproj     */
__device__ half g_Whi[RES * RES],   g_Wlo[RES * RES];       /* WresT      */
__device__ half g_WinHi[RES * INDIM], g_WinLo[RES * INDIM]; /* WinT       */
__device__ half g_xhi[NROWS * INDIM], g_xlo[NROWS * INDIM]; /* input      */

/* ====================== helpers ====================== */
__device__ __forceinline__ uint32_t smem_u32(const void* p) {
    uint32_t a;
    asm("{ .reg .u64 t; cvta.to.shared.u64 t, %1; cvt.u32.u64 %0, t; }" : "=r"(a) : "l"(p));
    return a;
}
__device__ __forceinline__ void cpasync16(uint32_t dst, const void* src) {
    asm volatile("cp.async.cg.shared.global [%0], [%1], 16;" :: "r"(dst), "l"(src));
}
__device__ __forceinline__ void cp_commit() { asm volatile("cp.async.commit_group;" ::: "memory"); }
__device__ __forceinline__ void cp_wait1()  { asm volatile("cp.async.wait_group 1;" ::: "memory"); }
__device__ __forceinline__ void cp_wait0()  { asm volatile("cp.async.wait_group 0;" ::: "memory"); }

__device__ __forceinline__ void ldsm4(uint32_t* r, uint32_t addr) {
    asm volatile("ldmatrix.sync.aligned.m8n8.x4.shared.b16 {%0,%1,%2,%3}, [%4];"
        : "=r"(r[0]), "=r"(r[1]), "=r"(r[2]), "=r"(r[3]) : "r"(addr));
}
__device__ __forceinline__ void mma16816(float* d, const uint32_t* a, uint32_t b0, uint32_t b1) {
    asm volatile(
        "mma.sync.aligned.m16n8k16.row.col.f32.f16.f16.f32 "
        "{%0,%1,%2,%3},{%4,%5,%6,%7},{%8,%9},{%0,%1,%2,%3};"
        : "+f"(d[0]), "+f"(d[1]), "+f"(d[2]), "+f"(d[3])
        : "r"(a[0]), "r"(a[1]), "r"(a[2]), "r"(a[3]), "r"(b0), "r"(b1));
}
__device__ __forceinline__ void split16(float f, half& h, half& l) {
    h = __float2half_rn(f);
    l = __float2half_rn(f - __half2float(h));
}
__device__ __forceinline__ float2 rec2(half2 h, half2 l) {
    float2 fh = __half22float2(h), fl = __half22float2(l);
    return make_float2(fh.x + fl.x, fh.y + fl.y);
}

/* ============ fp16x3 GEMM kernel (mma.sync m16n8k16) ====================== */
#define A_PLANE 8192
#define B_PLANE 8192
#define STAGE_B 32768
#define SMEM_DYN (3*STAGE_B)   /* 98304 */

__global__ __launch_bounds__(256, 2) void tc_kernel(
    int mode, int s, int flip, const float* __restrict__ lam)
{
    extern __shared__ char smem[];
    const uint32_t smem_u = smem_u32(smem);

    const int tid = threadIdx.x;
    const int wid = tid >> 5, lane = tid & 31;
    const int gid = lane >> 2, tig = lane & 3;
    const int m = lane >> 3, l7 = lane & 7;
    const int warpM = wid >> 2, warpN = wid & 3;
    const int rowBase = warpM * 64, colBase = warpN * 32;

    int row0, col0;
    if (mode == 1) {
        int x = blockIdx.x, ti = 0;
        while ((ti + 1) * (ti + 2) / 2 <= x) ti++;
        int tj = x - ti * (ti + 1) / 2;
        row0 = ti * 128; col0 = tj * 128;
    } else {
        row0 = blockIdx.y * 128; col0 = blockIdx.x * 128;
    }

    const half *Ahi, *Alo, *Bhi, *Blo; int K;
    if (mode == 0) {
        Ahi = flip ? g_Shi1 : g_Shi0; Alo = flip ? g_Slo1 : g_Slo0;
        Bhi = g_Whi; Blo = g_Wlo; K = RES;
    } else if (mode == 1) {
        size_t base = (size_t)blockIdx.z * TLEN * RES;
        Ahi = g_rshi + base; Alo = g_rslo + base;
        Bhi = Ahi; Blo = Alo; K = RES;
    } else {
        Ahi = g_xhi; Alo = g_xlo; Bhi = g_WinHi; Blo = g_WinLo; K = INDIM;
    }
    const int nIter = K >> 5;

    float acc[4][4][4] = {};

    uint32_t aRB[4], aX[4], bRB[2], bX[2];
    #pragma unroll
    for (int mt = 0; mt < 4; mt++) {
        uint32_t r = rowBase + mt * 16 + (m & 1) * 8 + l7;
        aRB[mt] = r * 64; aX[mt] = (r >> 1) & 3;
    }
    #pragma unroll
    for (int np = 0; np < 2; np++) {
        uint32_t n = colBase + (np * 2 + (m >> 1)) * 8 + l7;
        bRB[np] = n * 64; bX[np] = (n >> 1) & 3;
    }
    const uint32_t amk = (uint32_t)(m >> 1);
    const uint32_t bmk = (uint32_t)(m & 1);

    auto load_chunk = [&](int it, int stage) {
        const int k0 = it << 5;
        const uint32_t sb = smem_u + (uint32_t)stage * STAGE_B;
        #pragma unroll
        for (int q = 0; q < 8; q++) {
            int idx = tid + q * 256;
            int op = idx >> 10;
            int j = idx & 1023;
            int p = j >> 9, r = (j >> 2) & 127, c = j & 3;
            const half* gp = op ? (p ? Blo : Bhi) : (p ? Alo : Ahi);
            int rowg = (op ? col0 : row0) + r;
            const half* src = gp + (size_t)rowg * K + k0 + c * 8;
            uint32_t dst = sb + (uint32_t)op * (2 * A_PLANE) + (uint32_t)p * A_PLANE
                         + (uint32_t)r * 64 + (uint32_t)((c ^ ((r >> 1) & 3)) * 16);
            cpasync16(dst, src);
        }
    };

    load_chunk(0, 0);
    cp_commit();
    if (nIter > 1) { load_chunk(1, 1); cp_commit(); }

    for (int it = 0; it < nIter; ++it) {
        if (it + 1 < nIter) cp_wait1(); else cp_wait0();
        __syncthreads();
        if (it + 2 < nIter) { load_chunk(it + 2, (it + 2) % 3); cp_commit(); }

        const uint32_t sb = smem_u + (uint32_t)(it % 3) * STAGE_B;
        const uint32_t pAh = sb, pAl = sb + A_PLANE;
        const uint32_t pBh = sb + 2 * A_PLANE, pBl = pBh + B_PLANE;
        #pragma unroll
        for (int h16 = 0; h16 < 2; h16++) {
            uint32_t bh[2][4], bl[2][4];
            #pragma unroll
            for (int np = 0; np < 2; np++) {
                uint32_t off = bRB[np] + (((h16 * 2 + bmk) ^ bX[np]) * 16);
                ldsm4(bh[np], pBh + off);
                ldsm4(bl[np], pBl + off);
            }
            #pragma unroll
            for (int mt = 0; mt < 4; mt++) {
                uint32_t ah[4], al[4];
                uint32_t off = aRB[mt] + (((h16 * 2 + amk) ^ aX[mt]) * 16);
                ldsm4(ah, pAh + off);
                ldsm4(al, pAl + off);
                #pragma unroll
                for (int nt = 0; nt < 4; nt++) {
                    uint32_t b0h = bh[nt >> 1][(nt & 1) * 2], b1h = bh[nt >> 1][(nt & 1) * 2 + 1];
                    uint32_t b0l = bl[nt >> 1][(nt & 1) * 2], b1l = bl[nt >> 1][(nt & 1) * 2 + 1];
                    mma16816(acc[mt][nt], ah, b0h, b1h);
                    mma16816(acc[mt][nt], ah, b0l, b1l);
                    mma16816(acc[mt][nt], al, b0h, b1h);
                }
            }
        }
    }

    /* -------------------- epilogue (register -> global, planes only) ------- */
    float regc = 0.f;
    if (mode == 1) { float l = lam[0]; regc = log1pf(expf(l)); }
    const half* SoHi = flip ? g_Shi1 : g_Shi0;
    const half* SoLo = flip ? g_Slo1 : g_Slo0;
    half* ShiN = flip ? g_Shi0 : g_Shi1;
    half* SloN = flip ? g_Slo0 : g_Slo1;

    #pragma unroll
    for (int mt = 0; mt < 4; mt++)
        #pragma unroll
        for (int nt = 0; nt < 4; nt++)
            #pragma unroll
            for (int h = 0; h < 2; h++) {
                int grow = row0 + rowBase + mt * 16 + gid + h * 8;
                int col = col0 + colBase + nt * 8 + tig * 2;
                float cx = acc[mt][nt][h * 2 + 0];
                float cy = acc[mt][nt][h * 2 + 1];
                if (mode == 0) {
                    int b = grow >> 7, w = grow & 127;
                    int t = 4 * w + s - 2;
                    size_t so_off = (size_t)grow * RES + col;
                    float2 so = rec2(*(const half2*)&SoHi[so_off],
                                     *(const half2*)&SoLo[so_off]);
                    float2 u = make_float2(0.f, 0.f);
                    if (t >= 0) {
                        size_t uo = ((size_t)(b << 9) + t) * RES + col;
                        u = rec2(*(const half2*)&g_iphi[uo], *(const half2*)&g_iplo[uo]);
                    }
                    float2 v;
                    v.x = 0.7f * so.x + 0.3f * sinf(cx + u.x);
                    v.y = 0.7f * so.y + 0.3f * sinf(cy + u.y);
                    half hx, lx, hy, ly;
                    split16(v.x, hx, lx); split16(v.y, hy, ly);
                    *(half2*)&ShiN[so_off] = __halves2half2(hx, hy);
                    *(half2*)&SloN[so_off] = __halves2half2(lx, ly);
                    if (s >= 2) {
                        size_t ro = ((size_t)(b << 9) + t) * RES + col;
                        *(half2*)&g_rshi[ro] = __halves2half2(hx, hy);
                        *(half2*)&g_rslo[ro] = __halves2half2(lx, ly);
                    }
                } else if (mode == 1) {
                    float* Abm = g_A + (size_t)blockIdx.z * TLEN * TLEN;
                    float2 v;
                    v.x = cx + 1.0f + ((grow == col + 0) ? regc : 0.f);
                    v.y = cy + 1.0f + ((grow == col + 1) ? regc : 0.f);
                    *(float2*)&Abm[(size_t)grow * TLEN + col] = v;
                } else {
                    half hx, lx, hy, ly;
                    split16(cx, hx, lx); split16(cy, hy, ly);
                    size_t off = (size_t)grow * RES + col;
                    *(half2*)&g_iphi[off] = __halves2half2(hx, hy);
                    *(half2*)&g_iplo[off] = __halves2half2(lx, ly);
                }
            }
}

/* ============ split+transpose weights: dst[c][r] = split(src[r][c]) ======= */
__global__ void split_trans_kernel(const float* __restrict__ src, int rows, int cols, int which)
{
    half* dh = which ? g_WinHi : g_Whi;
    half* dl = which ? g_WinLo : g_Wlo;
    __shared__ float t[32][33];
    int c0 = blockIdx.x * 32, r0 = blockIdx.y * 32;
    for (int j = threadIdx.y; j < 32; j += 8)
        t[j][threadIdx.x] = src[(size_t)(r0 + j) * cols + c0 + threadIdx.x];
    __syncthreads();
    for (int j = threadIdx.y; j < 32; j += 8) {
        float f = t[threadIdx.x][j];
        half h, l; split16(f, h, l);
        size_t o = (size_t)(c0 + j) * rows + r0 + threadIdx.x;
        dh[o] = h; dl[o] = l;
    }
}

/* ============ split input rows (no transpose) ============================= */
__global__ void split_input_kernel(const float* __restrict__ src)
{
    int idx = blockIdx.x * 256 + threadIdx.x;
    float f = src[idx];
    half h, l; split16(f, h, l);
    g_xhi[idx] = h; g_xlo[idx] = l;
}

/* =================== step s=0 (state was zero), half2-wide ================ */
__global__ __launch_bounds__(256) void init0_kernel()
{
    int idx = blockIdx.x * 256 + threadIdx.x;
    int row = idx >> 10, q2 = (idx & 1023) * 2;
    int b = row >> 7, w = row & 127;
    int t = 4 * w - 2;
    half2 ph = __float2half2_rn(0.f), pl = ph;
    if (t >= 0) {
        size_t uo = ((size_t)(b << 9) + t) * RES + q2;
        float2 u = rec2(*(const half2*)&g_iphi[uo], *(const half2*)&g_iplo[uo]);
        float vx = 0.3f * sinf(u.x), vy = 0.3f * sinf(u.y);
        half hx, lx, hy, ly;
        split16(vx, hx, lx); split16(vy, hy, ly);
        ph = __halves2half2(hx, hy); pl = __halves2half2(lx, ly);
    }
    size_t so = (size_t)row * RES + q2;
    *(half2*)&g_Shi0[so] = ph;
    *(half2*)&g_Slo0[so] = pl;
}

/* ====== transpose Cholesky factors (only blocks the solve reads) ========== */
__global__ void transL_kernel()
{
    const int b = blockIdx.z;
    int c0 = blockIdx.x * 32, r0 = blockIdx.y * 32;
    if (c0 > r0 + 31) return;
    const float* src = g_A + (size_t)b * TLEN * TLEN;
    float* dst = g_LT + (size_t)b * TLEN * TLEN;
    __shared__ float t[32][33];
    for (int j = threadIdx.y; j < 32; j += 8)
        t[j][threadIdx.x] = src[(size_t)(r0 + j) * TLEN + c0 + threadIdx.x];
    __syncthreads();
    for (int j = threadIdx.y; j < 32; j += 8)
        dst[(size_t)(c0 + j) * TLEN + r0 + threadIdx.x] = t[threadIdx.x][j];
}

/* ============ blocked Cholesky, NB=64 (2 barriers/iter) =================== */
__global__ __launch_bounds__(256) void chol_panel_kernel(int p)
{
    const int b = blockIdx.x;
    float* Ab = g_A + (size_t)b * TLEN * TLEN;
    const int jb = p * 64;
    __shared__ float L11[64][65];
    __shared__ float diag[64];
    const int tid = threadIdx.x;
    for (int idx = tid; idx < 64 * 64; idx += 256) {
        int r = idx >> 6, c = idx & 63;
        L11[r][c] = Ab[(jb + r) * TLEN + jb + c];
    }
    __syncthreads();
    for (int k = 0; k < 64; k++) {
        float sq = sqrtf(L11[k][k]);
        if (tid == k) diag[k] = sq;
        if (tid > k && tid < 64) L11[tid][k] /= sq;
        __syncthreads();
        for (int idx = tid; idx < 64 * 64; idx += 256) {
            int r = idx >> 6, c = idx & 63;
            if (r > k && c > k && c <= r) L11[r][c] -= L11[r][k] * L11[c][k];
        }
        __syncthreads();
    }
    for (int idx = tid; idx < 64 * 64; idx += 256) {
        int r = idx >> 6, c = idx & 63;
        if (c < r)       Ab[(jb + r) * TLEN + jb + c] = L11[r][c];
        else if (c == r) Ab[(jb + r) * TLEN + jb + c] = diag[r];
    }
    __syncthreads();
    const int mrows = TLEN - jb - 64;
    for (int r = tid; r < mrows; r += 256) {
        int i = jb + 64 + r;
        float a[64];
        #pragma unroll
        for (int c = 0; c < 64; c++) a[c] = Ab[i * TLEN + jb + c];
        #pragma unroll
        for (int k = 0; k < 64; k++) {
            float sv = a[k];
            #pragma unroll
            for (int q = 0; q < k; q++) sv -= a[q] * L11[k][q];
            a[k] = sv / diag[k];
        }
        #pragma unroll
        for (int c = 0; c < 64; c++) Ab[i * TLEN + jb + c] = a[c];
    }
}

__global__ __launch_bounds__(256) void chol_update_kernel(int p)
{
    const int jb = p * 64 + 64;
    int idx = blockIdx.x;
    int ti = 0;
    while ((ti + 1) * (ti + 2) / 2 <= idx) ti++;
    int tj = idx - ti * (ti + 1) / 2;
    const int b = blockIdx.y;
    float* Ab = g_A + (size_t)b * TLEN * TLEN;
    const int r0 = jb + ti * 64, c0 = jb + tj * 64;
    __shared__ float La[64][65], Lb[64][65];
    const int tid = threadIdx.x;
    for (int q = tid; q < 64 * 64; q += 256) {
        int r = q >> 6, c = q & 63;
        La[r][c] = Ab[(r0 + r) * TLEN + p * 64 + c];
        Lb[r][c] = Ab[(c0 + r) * TLEN + p * 64 + c];
    }
    __syncthreads();
    const int tx = tid & 15, ty = tid >> 4;
    float acc[4][4] = {};
    #pragma unroll
    for (int k = 0; k < 64; k++) {
        float ar[4], bc[4];
        #pragma unroll
        for (int i = 0; i < 4; i++) ar[i] = La[ty * 4 + i][k];
        #pragma unroll
        for (int j = 0; j < 4; j++) bc[j] = Lb[tx * 4 + j][k];
        #pragma unroll
        for (int i = 0; i < 4; i++)
            #pragma unroll
            for (int j = 0; j < 4; j++)
                acc[i][j] += ar[i] * bc[j];
    }
    #pragma unroll
    for (int i = 0; i < 4; i++)
        #pragma unroll
        for (int j = 0; j < 4; j++)
            Ab[(r0 + ty * 4 + i) * TLEN + c0 + tx * 4 + j] -= acc[i][j];
}

/* ============ triangular solves: RHS split 4-way per batch ================
   grid = BATCH*4; block bg handles RHS columns [bg*16, bg*16+16).
   Same sequential j-loop and per-column arithmetic order as the proven
   round-10/12 kernel -> bit-identical g_Z.                                */
#define RHSG 16
__global__ __launch_bounds__(512) void solve_kernel(const float* __restrict__ Y)
{
    const int b = blockIdx.x >> 2;
    const int o0 = (blockIdx.x & 3) * RHSG;
    const int i = threadIdx.x;
    const float* __restrict__ Ab = g_A + (size_t)b * TLEN * TLEN;
    const float* __restrict__ Lt = g_LT + (size_t)b * TLEN * TLEN;
    float acc[RHSG];
    #pragma unroll
    for (int o = 0; o < RHSG; o++) acc[o] = Y[((size_t)b * TLEN + i) * OUTD + o0 + o];
    __shared__ float zrow[RHSG];
    for (int j = 0; j < TLEN; j++) {
        if (i == j) {
            float dinv = 1.f / Ab[j * TLEN + j];
            #pragma unroll
            for (int o = 0; o < RHSG; o++) { acc[o] *= dinv; zrow[o] = acc[o]; }
        }
        __syncthreads();
        if (i > j) {
            float lij = Lt[j * TLEN + i];
            #pragma unroll
            for (int o = 0; o < RHSG; o++) acc[o] -= lij * zrow[o];
        }
        __syncthreads();
    }
    for (int j = TLEN - 1; j >= 0; j--) {
        if (i == j) {
            float dinv = 1.f / Ab[j * TLEN + j];
            #pragma unroll
            for (int o = 0; o < RHSG; o++) { acc[o] *= dinv; zrow[o] = acc[o]; }
        }
        __syncthreads();
        if (i < j) {
            float lji = Ab[j * TLEN + i];
            #pragma unroll
            for (int o = 0; o < RHSG; o++) acc[o] -= lji * zrow[o];
        }
        __syncthreads();
    }
    #pragma unroll
    for (int o = 0; o < RHSG; o++) g_Z[((size_t)b * TLEN + i) * OUTD + o0 + o] = acc[o];
}

/* ============ W = Xb^T Z  (2048 x 64, K=512), X from rs planes ============ */
__global__ __launch_bounds__(256) void wout_kernel(float* __restrict__ out)
{
    const int b = blockIdx.y;
    const half* __restrict__ Xh = g_rshi + (size_t)b * TLEN * RES;
    const half* __restrict__ Xl = g_rslo + (size_t)b * TLEN * RES;
    const float* __restrict__ Zb = g_Z + (size_t)b * TLEN * OUTD;
    const int d0 = blockIdx.x * 128;
    __shared__ float As2[16][132];
    __shared__ float Bs2[16][68];
    const int tid = threadIdx.x;
    const int lr = tid >> 4, lc = (tid & 15) * 4;
    const int ty = tid >> 4, tx = tid & 15;
    float acc[8][4] = {};
    for (int k0 = 0; k0 < TLEN; k0 += 16) {
        #pragma unroll
        for (int half64 = 0; half64 < 2; half64++) {
            size_t off = (size_t)(k0 + lr) * RES + d0 + lc + half64 * 64;
            half2 h0 = *(const half2*)&Xh[off],     h1 = *(const half2*)&Xh[off + 2];
            half2 l0 = *(const half2*)&Xl[off],     l1 = *(const half2*)&Xl[off + 2];
            float2 a0 = rec2(h0, l0), a1 = rec2(h1, l1);
            As2[lr][lc + half64 * 64 + 0] = a0.x;
            As2[lr][lc + half64 * 64 + 1] = a0.y;
            As2[lr][lc + half64 * 64 + 2] = a1.x;
            As2[lr][lc + half64 * 64 + 3] = a1.y;
        }
        *(float4*)&Bs2[lr][lc] = *(const float4*)&Zb[(k0 + lr) * OUTD + lc];
        __syncthreads();
        #pragma unroll
        for (int k = 0; k < 16; k++) {
            float fa[8], fb[4];
            *(float4*)&fa[0] = *(const float4*)&As2[k][ty * 8];
            *(float4*)&fa[4] = *(const float4*)&As2[k][ty * 8 + 4];
            *(float4*)&fb[0] = *(const float4*)&Bs2[k][tx * 4];
            #pragma unroll
            for (int i = 0; i < 8; i++)
                #pragma unroll
                for (int j = 0; j < 4; j++)
                    acc[i][j] += fa[i] * fb[j];
        }
        __syncthreads();
    }
    #pragma unroll
    for (int i = 0; i < 8; i++)
        #pragma unroll
        for (int j = 0; j < 4; j++)
            out[((size_t)b * RES + d0 + ty * 8 + i) * OUTD + tx * 4 + j] = acc[i][j];
}

__global__ void bias_kernel(float* __restrict__ out)
{
    const int b = blockIdx.x, o = threadIdx.x;
    float s = 0.f;
    for (int n = 0; n < TLEN; n++) s += g_Z[((size_t)b * TLEN + n) * OUTD + o];
    out[(size_t)BATCH * RES * OUTD + b * OUTD + o] = s;
}

/* ======================= launch ======================= */
extern "C" void kernel_launch(void* const* d_in, const int* in_sizes, int n_in,
                              void* d_out, int out_size)
{
    const float* input  = (const float*)d_in[0];
    const float* target = (const float*)d_in[1];
    const float* W_res  = (const float*)d_in[2];
    const float* W_in   = (const float*)d_in[3];
    const float* lam    = (const float*)d_in[4];
    float* out = (float*)d_out;

    cudaFuncSetAttribute(tc_kernel, cudaFuncAttributeMaxDynamicSharedMemorySize, SMEM_DYN);

    /* 0. split+transpose weights, split input */
    split_trans_kernel<<<dim3(RES / 32, RES / 32), dim3(32, 8)>>>(W_res, RES, RES, 0);
    split_trans_kernel<<<dim3(RES / 32, INDIM / 32), dim3(32, 8)>>>(W_in, INDIM, RES, 1);
    split_input_kernel<<<(NROWS * INDIM) / 256, 256>>>(input);

    /* 1. input projection (writes inproj planes) */
    tc_kernel<<<dim3(RES / 128, NROWS / 128), 256, SMEM_DYN>>>(2, 0, 0, nullptr);

    /* 2. reservoir (state lives only as hi/lo planes) */
    init0_kernel<<<(MROWS * RES / 2) / 256, 256>>>();
    int flip = 0;
    for (int s = 1; s <= 5; s++) {
        tc_kernel<<<dim3(RES / 128, MROWS / 128), 256, SMEM_DYN>>>(0, s, flip, nullptr);
        flip ^= 1;
    }

    /* 3. gram: 10 lower (128x128) tiles; upper triangle never read */
    tc_kernel<<<dim3(10, 1, BATCH), 256, SMEM_DYN>>>(1, 0, 0, lam);

    /* 4. batched blocked Cholesky */
    for (int p = 0; p < 8; p++) {
        chol_panel_kernel<<<BATCH, 256>>>(p);
        if (p < 7) {
            int mt = 7 - p;
            chol_update_kernel<<<dim3(mt * (mt + 1) / 2, BATCH), 256>>>(p);
        }
    }

    /* 4b. transpose L (live blocks only) for coalesced forward solve */
    transL_kernel<<<dim3(16, 16, BATCH), dim3(32, 8)>>>();

    /* 5. triangular solves, RHS split 4-way per batch */
    solve_kernel<<<BATCH * 4, 512>>>(target);

    /* 6. readout */
    wout_kernel<<<dim3(RES / 128, BATCH), 256>>>(out);
    bias_kernel<<<BATCH, 64>>>(out);

    (void)in_sizes; (void)n_in; (void)out_size;
}

// round 14
// speedup vs baseline: 1.2429x; 1.0080x over previous
#include <cuda_runtime.h>
#include <cuda_fp16.h>
#include <math.h>
#include <stdint.h>

#define BATCH 32
#define TLEN  512
#define INDIM 128
#define RES   2048
#define OUTD  64
#define NWIN  128
#define MROWS (BATCH*NWIN)   /* 4096  reservoir rows (b,w) */
#define NROWS (BATCH*TLEN)   /* 16384 time rows (b,t)      */

/* ---------------- scratch (device globals; no allocations) ---------------- */
__device__ float g_A[BATCH * TLEN * TLEN]; /* gram matrices          32 MB */
__device__ float g_LT[BATCH * TLEN * TLEN];/* L transposed           32 MB */
__device__ float g_Z[BATCH * TLEN * OUTD]; /* solve result            4 MB */
/* fp16 split planes (hi+lo reconstructs fp32 to ~2^-22) */
__device__ half g_Shi0[MROWS * RES], g_Slo0[MROWS * RES];   /* state ping */
__device__ half g_Shi1[MROWS * RES], g_Slo1[MROWS * RES];   /* state pong */
__device__ half g_rshi[NROWS * RES], g_rslo[NROWS * RES];   /* rs states  */
__device__ half g_iphi[NROWS * RES], g_iplo[NROWS * RES];   /* inproj     */
__device__ half g_Whi[RES * RES],   g_Wlo[RES * RES];       /* WresT      */
__device__ half g_WinHi[RES * INDIM], g_WinLo[RES * INDIM]; /* WinT       */
__device__ half g_xhi[NROWS * INDIM], g_xlo[NROWS * INDIM]; /* input      */

/* ====================== helpers ====================== */
__device__ __forceinline__ uint32_t smem_u32(const void* p) {
    uint32_t a;
    asm("{ .reg .u64 t; cvta.to.shared.u64 t, %1; cvt.u32.u64 %0, t; }" : "=r"(a) : "l"(p));
    return a;
}
__device__ __forceinline__ void cpasync16(uint32_t dst, const void* src) {
    asm volatile("cp.async.cg.shared.global [%0], [%1], 16;" :: "r"(dst), "l"(src));
}
__device__ __forceinline__ void cp_commit() { asm volatile("cp.async.commit_group;" ::: "memory"); }
__device__ __forceinline__ void cp_wait1()  { asm volatile("cp.async.wait_group 1;" ::: "memory"); }
__device__ __forceinline__ void cp_wait0()  { asm volatile("cp.async.wait_group 0;" ::: "memory"); }

__device__ __forceinline__ void ldsm4(uint32_t* r, uint32_t addr) {
    asm volatile("ldmatrix.sync.aligned.m8n8.x4.shared.b16 {%0,%1,%2,%3}, [%4];"
        : "=r"(r[0]), "=r"(r[1]), "=r"(r[2]), "=r"(r[3]) : "r"(addr));
}
__device__ __forceinline__ void mma16816(float* d, const uint32_t* a, uint32_t b0, uint32_t b1) {
    asm volatile(
        "mma.sync.aligned.m16n8k16.row.col.f32.f16.f16.f32 "
        "{%0,%1,%2,%3},{%4,%5,%6,%7},{%8,%9},{%0,%1,%2,%3};"
        : "+f"(d[0]), "+f"(d[1]), "+f"(d[2]), "+f"(d[3])
        : "r"(a[0]), "r"(a[1]), "r"(a[2]), "r"(a[3]), "r"(b0), "r"(b1));
}
__device__ __forceinline__ void split16(float f, half& h, half& l) {
    h = __float2half_rn(f);
    l = __float2half_rn(f - __half2float(h));
}
__device__ __forceinline__ float2 rec2(half2 h, half2 l) {
    float2 fh = __half22float2(h), fl = __half22float2(l);
    return make_float2(fh.x + fl.x, fh.y + fl.y);
}

/* ============ fp16x3 GEMM kernel (mma.sync m16n8k16) ====================== */
#define A_PLANE 8192
#define B_PLANE 8192
#define STAGE_B 32768
#define SMEM_DYN (3*STAGE_B)   /* 98304 */

__global__ __launch_bounds__(256, 2) void tc_kernel(
    int mode, int s, int flip, const float* __restrict__ lam)
{
    extern __shared__ char smem[];
    const uint32_t smem_u = smem_u32(smem);

    const int tid = threadIdx.x;
    const int wid = tid >> 5, lane = tid & 31;
    const int gid = lane >> 2, tig = lane & 3;
    const int m = lane >> 3, l7 = lane & 7;
    const int warpM = wid >> 2, warpN = wid & 3;
    const int rowBase = warpM * 64, colBase = warpN * 32;

    int row0, col0;
    if (mode == 1) {
        int x = blockIdx.x, ti = 0;
        while ((ti + 1) * (ti + 2) / 2 <= x) ti++;
        int tj = x - ti * (ti + 1) / 2;
        row0 = ti * 128; col0 = tj * 128;
    } else {
        row0 = blockIdx.y * 128; col0 = blockIdx.x * 128;
    }

    const half *Ahi, *Alo, *Bhi, *Blo; int K;
    if (mode == 0) {
        Ahi = flip ? g_Shi1 : g_Shi0; Alo = flip ? g_Slo1 : g_Slo0;
        Bhi = g_Whi; Blo = g_Wlo; K = RES;
    } else if (mode == 1) {
        size_t base = (size_t)blockIdx.z * TLEN * RES;
        Ahi = g_rshi + base; Alo = g_rslo + base;
        Bhi = Ahi; Blo = Alo; K = RES;
    } else {
        Ahi = g_xhi; Alo = g_xlo; Bhi = g_WinHi; Blo = g_WinLo; K = INDIM;
    }
    const int nIter = K >> 5;

    float acc[4][4][4] = {};

    uint32_t aRB[4], aX[4], bRB[2], bX[2];
    #pragma unroll
    for (int mt = 0; mt < 4; mt++) {
        uint32_t r = rowBase + mt * 16 + (m & 1) * 8 + l7;
        aRB[mt] = r * 64; aX[mt] = (r >> 1) & 3;
    }
    #pragma unroll
    for (int np = 0; np < 2; np++) {
        uint32_t n = colBase + (np * 2 + (m >> 1)) * 8 + l7;
        bRB[np] = n * 64; bX[np] = (n >> 1) & 3;
    }
    const uint32_t amk = (uint32_t)(m >> 1);
    const uint32_t bmk = (uint32_t)(m & 1);

    auto load_chunk = [&](int it, int stage) {
        const int k0 = it << 5;
        const uint32_t sb = smem_u + (uint32_t)stage * STAGE_B;
        #pragma unroll
        for (int q = 0; q < 8; q++) {
            int idx = tid + q * 256;
            int op = idx >> 10;
            int j = idx & 1023;
            int p = j >> 9, r = (j >> 2) & 127, c = j & 3;
            const half* gp = op ? (p ? Blo : Bhi) : (p ? Alo : Ahi);
            int rowg = (op ? col0 : row0) + r;
            const half* src = gp + (size_t)rowg * K + k0 + c * 8;
            uint32_t dst = sb + (uint32_t)op * (2 * A_PLANE) + (uint32_t)p * A_PLANE
                         + (uint32_t)r * 64 + (uint32_t)((c ^ ((r >> 1) & 3)) * 16);
            cpasync16(dst, src);
        }
    };

    load_chunk(0, 0);
    cp_commit();
    if (nIter > 1) { load_chunk(1, 1); cp_commit(); }

    for (int it = 0; it < nIter; ++it) {
        if (it + 1 < nIter) cp_wait1(); else cp_wait0();
        __syncthreads();
        if (it + 2 < nIter) { load_chunk(it + 2, (it + 2) % 3); cp_commit(); }

        const uint32_t sb = smem_u + (uint32_t)(it % 3) * STAGE_B;
        const uint32_t pAh = sb, pAl = sb + A_PLANE;
        const uint32_t pBh = sb + 2 * A_PLANE, pBl = pBh + B_PLANE;
        #pragma unroll
        for (int h16 = 0; h16 < 2; h16++) {
            uint32_t bh[2][4], bl[2][4];
            #pragma unroll
            for (int np = 0; np < 2; np++) {
                uint32_t off = bRB[np] + (((h16 * 2 + bmk) ^ bX[np]) * 16);
                ldsm4(bh[np], pBh + off);
                ldsm4(bl[np], pBl + off);
            }
            #pragma unroll
            for (int mt = 0; mt < 4; mt++) {
                uint32_t ah[4], al[4];
                uint32_t off = aRB[mt] + (((h16 * 2 + amk) ^ aX[mt]) * 16);
                ldsm4(ah, pAh + off);
                ldsm4(al, pAl + off);
                #pragma unroll
                for (int nt = 0; nt < 4; nt++) {
                    uint32_t b0h = bh[nt >> 1][(nt & 1) * 2], b1h = bh[nt >> 1][(nt & 1) * 2 + 1];
                    uint32_t b0l = bl[nt >> 1][(nt & 1) * 2], b1l = bl[nt >> 1][(nt & 1) * 2 + 1];
                    mma16816(acc[mt][nt], ah, b0h, b1h);
                    mma16816(acc[mt][nt], ah, b0l, b1l);
                    mma16816(acc[mt][nt], al, b0h, b1h);
                }
            }
        }
    }

    /* -------------------- epilogue (register -> global, planes only) ------- */
    float regc = 0.f;
    if (mode == 1) { float l = lam[0]; regc = log1pf(expf(l)); }
    const half* SoHi = flip ? g_Shi1 : g_Shi0;
    const half* SoLo = flip ? g_Slo1 : g_Slo0;
    half* ShiN = flip ? g_Shi0 : g_Shi1;
    half* SloN = flip ? g_Slo0 : g_Slo1;

    #pragma unroll
    for (int mt = 0; mt < 4; mt++)
        #pragma unroll
        for (int nt = 0; nt < 4; nt++)
            #pragma unroll
            for (int h = 0; h < 2; h++) {
                int grow = row0 + rowBase + mt * 16 + gid + h * 8;
                int col = col0 + colBase + nt * 8 + tig * 2;
                float cx = acc[mt][nt][h * 2 + 0];
                float cy = acc[mt][nt][h * 2 + 1];
                if (mode == 0) {
                    int b = grow >> 7, w = grow & 127;
                    int t = 4 * w + s - 2;
                    size_t so_off = (size_t)grow * RES + col;
                    float2 so = rec2(*(const half2*)&SoHi[so_off],
                                     *(const half2*)&SoLo[so_off]);
                    float2 u = make_float2(0.f, 0.f);
                    if (t >= 0) {
                        size_t uo = ((size_t)(b << 9) + t) * RES + col;
                        u = rec2(*(const half2*)&g_iphi[uo], *(const half2*)&g_iplo[uo]);
                    }
                    float2 v;
                    v.x = 0.7f * so.x + 0.3f * sinf(cx + u.x);
                    v.y = 0.7f * so.y + 0.3f * sinf(cy + u.y);
                    half hx, lx, hy, ly;
                    split16(v.x, hx, lx); split16(v.y, hy, ly);
                    *(half2*)&ShiN[so_off] = __halves2half2(hx, hy);
                    *(half2*)&SloN[so_off] = __halves2half2(lx, ly);
                    if (s >= 2) {
                        size_t ro = ((size_t)(b << 9) + t) * RES + col;
                        *(half2*)&g_rshi[ro] = __halves2half2(hx, hy);
                        *(half2*)&g_rslo[ro] = __halves2half2(lx, ly);
                    }
                } else if (mode == 1) {
                    float* Abm = g_A + (size_t)blockIdx.z * TLEN * TLEN;
                    float2 v;
                    v.x = cx + 1.0f + ((grow == col + 0) ? regc : 0.f);
                    v.y = cy + 1.0f + ((grow == col + 1) ? regc : 0.f);
                    *(float2*)&Abm[(size_t)grow * TLEN + col] = v;
                } else {
                    half hx, lx, hy, ly;
                    split16(cx, hx, lx); split16(cy, hy, ly);
                    size_t off = (size_t)grow * RES + col;
                    *(half2*)&g_iphi[off] = __halves2half2(hx, hy);
                    *(half2*)&g_iplo[off] = __halves2half2(lx, ly);
                }
            }
}

/* ============ split+transpose weights: dst[c][r] = split(src[r][c]) ======= */
__global__ void split_trans_kernel(const float* __restrict__ src, int rows, int cols, int which)
{
    half* dh = which ? g_WinHi : g_Whi;
    half* dl = which ? g_WinLo : g_Wlo;
    __shared__ float t[32][33];
    int c0 = blockIdx.x * 32, r0 = blockIdx.y * 32;
    for (int j = threadIdx.y; j < 32; j += 8)
        t[j][threadIdx.x] = src[(size_t)(r0 + j) * cols + c0 + threadIdx.x];
    __syncthreads();
    for (int j = threadIdx.y; j < 32; j += 8) {
        float f = t[threadIdx.x][j];
        half h, l; split16(f, h, l);
        size_t o = (size_t)(c0 + j) * rows + r0 + threadIdx.x;
        dh[o] = h; dl[o] = l;
    }
}

/* ============ split input rows (no transpose) ============================= */
__global__ void split_input_kernel(const float* __restrict__ src)
{
    int idx = blockIdx.x * 256 + threadIdx.x;
    float f = src[idx];
    half h, l; split16(f, h, l);
    g_xhi[idx] = h; g_xlo[idx] = l;
}

/* =================== step s=0 (state was zero), half2-wide ================ */
__global__ __launch_bounds__(256) void init0_kernel()
{
    int idx = blockIdx.x * 256 + threadIdx.x;
    int row = idx >> 10, q2 = (idx & 1023) * 2;
    int b = row >> 7, w = row & 127;
    int t = 4 * w - 2;
    half2 ph = __float2half2_rn(0.f), pl = ph;
    if (t >= 0) {
        size_t uo = ((size_t)(b << 9) + t) * RES + q2;
        float2 u = rec2(*(const half2*)&g_iphi[uo], *(const half2*)&g_iplo[uo]);
        float vx = 0.3f * sinf(u.x), vy = 0.3f * sinf(u.y);
        half hx, lx, hy, ly;
        split16(vx, hx, lx); split16(vy, hy, ly);
        ph = __halves2half2(hx, hy); pl = __halves2half2(lx, ly);
    }
    size_t so = (size_t)row * RES + q2;
    *(half2*)&g_Shi0[so] = ph;
    *(half2*)&g_Slo0[so] = pl;
}

/* ============ blocked Cholesky, NB=64; also emits LT for its column block =
   After panel p, columns [jb, jb+64) of L are FINAL (trailing updates touch
   only columns >= jb+64), so LT rows [jb, jb+64) can be written here and
   the separate transpose kernel is eliminated.                             */
__global__ __launch_bounds__(256) void chol_panel_kernel(int p)
{
    const int b = blockIdx.x;
    float* Ab = g_A + (size_t)b * TLEN * TLEN;
    float* Lt = g_LT + (size_t)b * TLEN * TLEN;
    const int jb = p * 64;
    __shared__ float L11[64][65];
    __shared__ float diag[64];
    const int tid = threadIdx.x;
    for (int idx = tid; idx < 64 * 64; idx += 256) {
        int r = idx >> 6, c = idx & 63;
        L11[r][c] = Ab[(jb + r) * TLEN + jb + c];
    }
    __syncthreads();
    for (int k = 0; k < 64; k++) {
        float sq = sqrtf(L11[k][k]);
        if (tid == k) diag[k] = sq;
        if (tid > k && tid < 64) L11[tid][k] /= sq;
        __syncthreads();
        for (int idx = tid; idx < 64 * 64; idx += 256) {
            int r = idx >> 6, c = idx & 63;
            if (r > k && c > k && c <= r) L11[r][c] -= L11[r][k] * L11[c][k];
        }
        __syncthreads();
    }
    /* write diagonal block: L to A, and its transpose to LT (strict i>j only
       is read by the solve, include diag for simplicity)                    */
    for (int idx = tid; idx < 64 * 64; idx += 256) {
        int r = idx >> 6, c = idx & 63;
        float v = (c < r) ? L11[r][c] : (c == r ? diag[r] : 0.f);
        if (c <= r) {
            Ab[(jb + r) * TLEN + jb + c] = v;
            Lt[(size_t)(jb + c) * TLEN + jb + r] = v;   /* LT[j][i]=L[i][j] */
        }
    }
    __syncthreads();
    const int mrows = TLEN - jb - 64;
    for (int r = tid; r < mrows; r += 256) {
        int i = jb + 64 + r;
        float a[64];
        #pragma unroll
        for (int c = 0; c < 64; c++) a[c] = Ab[i * TLEN + jb + c];
        #pragma unroll
        for (int k = 0; k < 64; k++) {
            float sv = a[k];
            #pragma unroll
            for (int q = 0; q < k; q++) sv -= a[q] * L11[k][q];
            a[k] = sv / diag[k];
        }
        #pragma unroll
        for (int c = 0; c < 64; c++) {
            Ab[i * TLEN + jb + c] = a[c];
            Lt[(size_t)(jb + c) * TLEN + i] = a[c];     /* coalesced per c */
        }
    }
}

__global__ __launch_bounds__(256) void chol_update_kernel(int p)
{
    const int jb = p * 64 + 64;
    int idx = blockIdx.x;
    int ti = 0;
    while ((ti + 1) * (ti + 2) / 2 <= idx) ti++;
    int tj = idx - ti * (ti + 1) / 2;
    const int b = blockIdx.y;
    float* Ab = g_A + (size_t)b * TLEN * TLEN;
    const int r0 = jb + ti * 64, c0 = jb + tj * 64;
    __shared__ float La[64][65], Lb[64][65];
    const int tid = threadIdx.x;
    for (int q = tid; q < 64 * 64; q += 256) {
        int r = q >> 6, c = q & 63;
        La[r][c] = Ab[(r0 + r) * TLEN + p * 64 + c];
        Lb[r][c] = Ab[(c0 + r) * TLEN + p * 64 + c];
    }
    __syncthreads();
    const int tx = tid & 15, ty = tid >> 4;
    float acc[4][4] = {};
    #pragma unroll
    for (int k = 0; k < 64; k++) {
        float ar[4], bc[4];
        #pragma unroll
        for (int i = 0; i < 4; i++) ar[i] = La[ty * 4 + i][k];
        #pragma unroll
        for (int j = 0; j < 4; j++) bc[j] = Lb[tx * 4 + j][k];
        #pragma unroll
        for (int i = 0; i < 4; i++)
            #pragma unroll
            for (int j = 0; j < 4; j++)
                acc[i][j] += ar[i] * bc[j];
    }
    #pragma unroll
    for (int i = 0; i < 4; i++)
        #pragma unroll
        for (int j = 0; j < 4; j++)
            Ab[(r0 + ty * 4 + i) * TLEN + c0 + tx * 4 + j] -= acc[i][j];
}

/* ============ triangular solves: RHS split 8-way per batch ================
   grid = BATCH*8; block bg handles RHS columns [bg*8, bg*8+8).
   Same sequential j-loop and per-column order -> bit-identical g_Z.       */
#define RHSG 8
__global__ __launch_bounds__(512) void solve_kernel(const float* __restrict__ Y)
{
    const int b = blockIdx.x >> 3;
    const int o0 = (blockIdx.x & 7) * RHSG;
    const int i = threadIdx.x;
    const float* __restrict__ Ab = g_A + (size_t)b * TLEN * TLEN;
    const float* __restrict__ Lt = g_LT + (size_t)b * TLEN * TLEN;
    float acc[RHSG];
    #pragma unroll
    for (int o = 0; o < RHSG; o++) acc[o] = Y[((size_t)b * TLEN + i) * OUTD + o0 + o];
    __shared__ float zrow[RHSG];
    for (int j = 0; j < TLEN; j++) {
        if (i == j) {
            float dinv = 1.f / Ab[j * TLEN + j];
            #pragma unroll
            for (int o = 0; o < RHSG; o++) { acc[o] *= dinv; zrow[o] = acc[o]; }
        }
        __syncthreads();
        if (i > j) {
            float lij = Lt[j * TLEN + i];
            #pragma unroll
            for (int o = 0; o < RHSG; o++) acc[o] -= lij * zrow[o];
        }
        __syncthreads();
    }
    for (int j = TLEN - 1; j >= 0; j--) {
        if (i == j) {
            float dinv = 1.f / Ab[j * TLEN + j];
            #pragma unroll
            for (int o = 0; o < RHSG; o++) { acc[o] *= dinv; zrow[o] = acc[o]; }
        }
        __syncthreads();
        if (i < j) {
            float lji = Ab[j * TLEN + i];
            #pragma unroll
            for (int o = 0; o < RHSG; o++) acc[o] -= lji * zrow[o];
        }
        __syncthreads();
    }
    #pragma unroll
    for (int o = 0; o < RHSG; o++) g_Z[((size_t)b * TLEN + i) * OUTD + o0 + o] = acc[o];
}

/* ============ W = Xb^T Z  (2048 x 64, K=512), X from rs planes ============ */
__global__ __launch_bounds__(256) void wout_kernel(float* __restrict__ out)
{
    const int b = blockIdx.y;
    const half* __restrict__ Xh = g_rshi + (size_t)b * TLEN * RES;
    const half* __restrict__ Xl = g_rslo + (size_t)b * TLEN * RES;
    const float* __restrict__ Zb = g_Z + (size_t)b * TLEN * OUTD;
    const int d0 = blockIdx.x * 128;
    __shared__ float As2[16][132];
    __shared__ float Bs2[16][68];
    const int tid = threadIdx.x;
    const int lr = tid >> 4, lc = (tid & 15) * 4;
    const int ty = tid >> 4, tx = tid & 15;
    float acc[8][4] = {};
    for (int k0 = 0; k0 < TLEN; k0 += 16) {
        #pragma unroll
        for (int half64 = 0; half64 < 2; half64++) {
            size_t off = (size_t)(k0 + lr) * RES + d0 + lc + half64 * 64;
            half2 h0 = *(const half2*)&Xh[off],     h1 = *(const half2*)&Xh[off + 2];
            half2 l0 = *(const half2*)&Xl[off],     l1 = *(const half2*)&Xl[off + 2];
            float2 a0 = rec2(h0, l0), a1 = rec2(h1, l1);
            As2[lr][lc + half64 * 64 + 0] = a0.x;
            As2[lr][lc + half64 * 64 + 1] = a0.y;
            As2[lr][lc + half64 * 64 + 2] = a1.x;
            As2[lr][lc + half64 * 64 + 3] = a1.y;
        }
        *(float4*)&Bs2[lr][lc] = *(const float4*)&Zb[(k0 + lr) * OUTD + lc];
        __syncthreads();
        #pragma unroll
        for (int k = 0; k < 16; k++) {
            float fa[8], fb[4];
            *(float4*)&fa[0] = *(const float4*)&As2[k][ty * 8];
            *(float4*)&fa[4] = *(const float4*)&As2[k][ty * 8 + 4];
            *(float4*)&fb[0] = *(const float4*)&Bs2[k][tx * 4];
            #pragma unroll
            for (int i = 0; i < 8; i++)
                #pragma unroll
                for (int j = 0; j < 4; j++)
                    acc[i][j] += fa[i] * fb[j];
        }
        __syncthreads();
    }
    #pragma unroll
    for (int i = 0; i < 8; i++)
        #pragma unroll
        for (int j = 0; j < 4; j++)
            out[((size_t)b * RES + d0 + ty * 8 + i) * OUTD + tx * 4 + j] = acc[i][j];
}

/* ============ bias: 256 threads, (b,o) flattened ========================== */
__global__ void bias_kernel(float* __restrict__ out)
{
    int idx = blockIdx.x * 256 + threadIdx.x;   /* over BATCH*OUTD = 2048 */
    if (idx >= BATCH * OUTD) return;
    int b = idx >> 6, o = idx & 63;
    float s = 0.f;
    for (int n = 0; n < TLEN; n++) s += g_Z[((size_t)b * TLEN + n) * OUTD + o];
    out[(size_t)BATCH * RES * OUTD + b * OUTD + o] = s;
}

/* ======================= launch ======================= */
extern "C" void kernel_launch(void* const* d_in, const int* in_sizes, int n_in,
                              void* d_out, int out_size)
{
    const float* input  = (const float*)d_in[0];
    const float* target = (const float*)d_in[1];
    const float* W_res  = (const float*)d_in[2];
    const float* W_in   = (const float*)d_in[3];
    const float* lam    = (const float*)d_in[4];
    float* out = (float*)d_out;

    cudaFuncSetAttribute(tc_kernel, cudaFuncAttributeMaxDynamicSharedMemorySize, SMEM_DYN);

    /* 0. split+transpose weights, split input */
    split_trans_kernel<<<dim3(RES / 32, RES / 32), dim3(32, 8)>>>(W_res, RES, RES, 0);
    split_trans_kernel<<<dim3(RES / 32, INDIM / 32), dim3(32, 8)>>>(W_in, INDIM, RES, 1);
    split_input_kernel<<<(NROWS * INDIM) / 256, 256>>>(input);

    /* 1. input projection (writes inproj planes) */
    tc_kernel<<<dim3(RES / 128, NROWS / 128), 256, SMEM_DYN>>>(2, 0, 0, nullptr);

    /* 2. reservoir (state lives only as hi/lo planes) */
    init0_kernel<<<(MROWS * RES / 2) / 256, 256>>>();
    int flip = 0;
    for (int s = 1; s <= 5; s++) {
        tc_kernel<<<dim3(RES / 128, MROWS / 128), 256, SMEM_DYN>>>(0, s, flip, nullptr);
        flip ^= 1;
    }

    /* 3. gram: 10 lower (128x128) tiles; upper triangle never read */
    tc_kernel<<<dim3(10, 1, BATCH), 256, SMEM_DYN>>>(1, 0, 0, lam);

    /* 4. batched blocked Cholesky (panel also emits LT column block) */
    for (int p = 0; p < 8; p++) {
        chol_panel_kernel<<<BATCH, 256>>>(p);
        if (p < 7) {
            int mt = 7 - p;
            chol_update_kernel<<<dim3(mt * (mt + 1) / 2, BATCH), 256>>>(p);
        }
    }

    /* 5. triangular solves, RHS split 8-way per batch */
    solve_kernel<<<BATCH * 8, 512>>>(target);

    /* 6. readout */
    wout_kernel<<<dim3(RES / 128, BATCH), 256>>>(out);
    bias_kernel<<<(BATCH * OUTD + 255) / 256, 256>>>(out);

    (void)in_sizes; (void)n_in; (void)out_size;
}

// round 15
// speedup vs baseline: 1.2732x; 1.0244x over previous
#include <cuda_runtime.h>
#include <cuda_fp16.h>
#include <math.h>
#include <stdint.h>

#define BATCH 32
#define TLEN  512
#define INDIM 128
#define RES   2048
#define OUTD  64
#define NWIN  128
#define MROWS (BATCH*NWIN)   /* 4096  reservoir rows (b,w) */
#define NROWS (BATCH*TLEN)   /* 16384 time rows (b,t)      */

/* ---------------- scratch (device globals; no allocations) ---------------- */
__device__ float g_A[BATCH * TLEN * TLEN]; /* gram matrices          32 MB */
__device__ float g_LT[BATCH * TLEN * TLEN];/* L transposed           32 MB */
__device__ float g_Z[BATCH * TLEN * OUTD]; /* solve result            4 MB */
/* fp16 split planes (hi+lo reconstructs fp32 to ~2^-22) */
__device__ half g_Shi0[MROWS * RES], g_Slo0[MROWS * RES];   /* state ping */
__device__ half g_Shi1[MROWS * RES], g_Slo1[MROWS * RES];   /* state pong */
__device__ half g_rshi[NROWS * RES], g_rslo[NROWS * RES];   /* rs states  */
__device__ half g_iphi[NROWS * RES], g_iplo[NROWS * RES];   /* inproj     */
__device__ half g_Whi[RES * RES],   g_Wlo[RES * RES];       /* WresT      */
__device__ half g_WinHi[RES * INDIM], g_WinLo[RES * INDIM]; /* WinT       */
__device__ half g_xhi[NROWS * INDIM], g_xlo[NROWS * INDIM]; /* input      */

/* ====================== helpers ====================== */
__device__ __forceinline__ uint32_t smem_u32(const void* p) {
    uint32_t a;
    asm("{ .reg .u64 t; cvta.to.shared.u64 t, %1; cvt.u32.u64 %0, t; }" : "=r"(a) : "l"(p));
    return a;
}
__device__ __forceinline__ void cpasync16(uint32_t dst, const void* src) {
    asm volatile("cp.async.cg.shared.global [%0], [%1], 16;" :: "r"(dst), "l"(src));
}
__device__ __forceinline__ void cp_commit() { asm volatile("cp.async.commit_group;" ::: "memory"); }
__device__ __forceinline__ void cp_wait1()  { asm volatile("cp.async.wait_group 1;" ::: "memory"); }
__device__ __forceinline__ void cp_wait0()  { asm volatile("cp.async.wait_group 0;" ::: "memory"); }

__device__ __forceinline__ void ldsm4(uint32_t* r, uint32_t addr) {
    asm volatile("ldmatrix.sync.aligned.m8n8.x4.shared.b16 {%0,%1,%2,%3}, [%4];"
        : "=r"(r[0]), "=r"(r[1]), "=r"(r[2]), "=r"(r[3]) : "r"(addr));
}
__device__ __forceinline__ void mma16816(float* d, const uint32_t* a, uint32_t b0, uint32_t b1) {
    asm volatile(
        "mma.sync.aligned.m16n8k16.row.col.f32.f16.f16.f32 "
        "{%0,%1,%2,%3},{%4,%5,%6,%7},{%8,%9},{%0,%1,%2,%3};"
        : "+f"(d[0]), "+f"(d[1]), "+f"(d[2]), "+f"(d[3])
        : "r"(a[0]), "r"(a[1]), "r"(a[2]), "r"(a[3]), "r"(b0), "r"(b1));
}
__device__ __forceinline__ void split16(float f, half& h, half& l) {
    h = __float2half_rn(f);
    l = __float2half_rn(f - __half2float(h));
}
__device__ __forceinline__ float2 rec2(half2 h, half2 l) {
    float2 fh = __half22float2(h), fl = __half22float2(l);
    return make_float2(fh.x + fl.x, fh.y + fl.y);
}

/* ============ fp16x3 GEMM kernel (mma.sync m16n8k16) ====================== */
#define A_PLANE 8192
#define B_PLANE 8192
#define STAGE_B 32768
#define SMEM_DYN (3*STAGE_B)   /* 98304 */

__global__ __launch_bounds__(256, 2) void tc_kernel(
    int mode, int s, int flip, const float* __restrict__ lam)
{
    extern __shared__ char smem[];
    const uint32_t smem_u = smem_u32(smem);

    const int tid = threadIdx.x;
    const int wid = tid >> 5, lane = tid & 31;
    const int gid = lane >> 2, tig = lane & 3;
    const int m = lane >> 3, l7 = lane & 7;
    const int warpM = wid >> 2, warpN = wid & 3;
    const int rowBase = warpM * 64, colBase = warpN * 32;

    int row0, col0;
    if (mode == 1) {
        int x = blockIdx.x, ti = 0;
        while ((ti + 1) * (ti + 2) / 2 <= x) ti++;
        int tj = x - ti * (ti + 1) / 2;
        row0 = ti * 128; col0 = tj * 128;
    } else {
        row0 = blockIdx.y * 128; col0 = blockIdx.x * 128;
    }
    const int diag = (mode == 1) && (row0 == col0);   /* A tile == B tile */

    const half *Ahi, *Alo, *Bhi, *Blo; int K;
    if (mode == 0) {
        Ahi = flip ? g_Shi1 : g_Shi0; Alo = flip ? g_Slo1 : g_Slo0;
        Bhi = g_Whi; Blo = g_Wlo; K = RES;
    } else if (mode == 1) {
        size_t base = (size_t)blockIdx.z * TLEN * RES;
        Ahi = g_rshi + base; Alo = g_rslo + base;
        Bhi = Ahi; Blo = Alo; K = RES;
    } else {
        Ahi = g_xhi; Alo = g_xlo; Bhi = g_WinHi; Blo = g_WinLo; K = INDIM;
    }
    const int nIter = K >> 5;

    float acc[4][4][4] = {};

    uint32_t aRB[4], aX[4], bRB[2], bX[2];
    #pragma unroll
    for (int mt = 0; mt < 4; mt++) {
        uint32_t r = rowBase + mt * 16 + (m & 1) * 8 + l7;
        aRB[mt] = r * 64; aX[mt] = (r >> 1) & 3;
    }
    #pragma unroll
    for (int np = 0; np < 2; np++) {
        uint32_t n = colBase + (np * 2 + (m >> 1)) * 8 + l7;
        bRB[np] = n * 64; bX[np] = (n >> 1) & 3;
    }
    const uint32_t amk = (uint32_t)(m >> 1);
    const uint32_t bmk = (uint32_t)(m & 1);

    auto load_chunk = [&](int it, int stage) {
        const int k0 = it << 5;
        const uint32_t sb = smem_u + (uint32_t)stage * STAGE_B;
        #pragma unroll
        for (int q = 0; q < 8; q++) {
            int idx = tid + q * 256;
            int op = idx >> 10;
            if (diag && op) continue;          /* B aliases A for diag tiles */
            int j = idx & 1023;
            int p = j >> 9, r = (j >> 2) & 127, c = j & 3;
            const half* gp = op ? (p ? Blo : Bhi) : (p ? Alo : Ahi);
            int rowg = (op ? col0 : row0) + r;
            const half* src = gp + (size_t)rowg * K + k0 + c * 8;
            uint32_t dst = sb + (uint32_t)op * (2 * A_PLANE) + (uint32_t)p * A_PLANE
                         + (uint32_t)r * 64 + (uint32_t)((c ^ ((r >> 1) & 3)) * 16);
            cpasync16(dst, src);
        }
    };

    load_chunk(0, 0);
    cp_commit();
    if (nIter > 1) { load_chunk(1, 1); cp_commit(); }

    for (int it = 0; it < nIter; ++it) {
        if (it + 1 < nIter) cp_wait1(); else cp_wait0();
        __syncthreads();
        if (it + 2 < nIter) { load_chunk(it + 2, (it + 2) % 3); cp_commit(); }

        const uint32_t sb = smem_u + (uint32_t)(it % 3) * STAGE_B;
        const uint32_t pAh = sb, pAl = sb + A_PLANE;
        const uint32_t pBh = diag ? pAh : sb + 2 * A_PLANE;
        const uint32_t pBl = diag ? pAl : sb + 2 * A_PLANE + B_PLANE;
        #pragma unroll
        for (int h16 = 0; h16 < 2; h16++) {
            uint32_t bh[2][4], bl[2][4];
            #pragma unroll
            for (int np = 0; np < 2; np++) {
                uint32_t off = bRB[np] + (((h16 * 2 + bmk) ^ bX[np]) * 16);
                ldsm4(bh[np], pBh + off);
                ldsm4(bl[np], pBl + off);
            }
            #pragma unroll
            for (int mt = 0; mt < 4; mt++) {
                uint32_t ah[4], al[4];
                uint32_t off = aRB[mt] + (((h16 * 2 + amk) ^ aX[mt]) * 16);
                ldsm4(ah, pAh + off);
                ldsm4(al, pAl + off);
                #pragma unroll
                for (int nt = 0; nt < 4; nt++) {
                    uint32_t b0h = bh[nt >> 1][(nt & 1) * 2], b1h = bh[nt >> 1][(nt & 1) * 2 + 1];
                    uint32_t b0l = bl[nt >> 1][(nt & 1) * 2], b1l = bl[nt >> 1][(nt & 1) * 2 + 1];
                    mma16816(acc[mt][nt], ah, b0h, b1h);
                    mma16816(acc[mt][nt], ah, b0l, b1l);
                    mma16816(acc[mt][nt], al, b0h, b1h);
                }
            }
        }
    }

    /* -------------------- epilogue (register -> global, planes only) ------- */
    float regc = 0.f;
    if (mode == 1) { float l = lam[0]; regc = log1pf(expf(l)); }
    const half* SoHi = flip ? g_Shi1 : g_Shi0;
    const half* SoLo = flip ? g_Slo1 : g_Slo0;
    half* ShiN = flip ? g_Shi0 : g_Shi1;
    half* SloN = flip ? g_Slo0 : g_Slo1;

    #pragma unroll
    for (int mt = 0; mt < 4; mt++)
        #pragma unroll
        for (int nt = 0; nt < 4; nt++)
            #pragma unroll
            for (int h = 0; h < 2; h++) {
                int grow = row0 + rowBase + mt * 16 + gid + h * 8;
                int col = col0 + colBase + nt * 8 + tig * 2;
                float cx = acc[mt][nt][h * 2 + 0];
                float cy = acc[mt][nt][h * 2 + 1];
                if (mode == 0) {
                    int b = grow >> 7, w = grow & 127;
                    int t = 4 * w + s - 2;
                    size_t so_off = (size_t)grow * RES + col;
                    float2 so = rec2(*(const half2*)&SoHi[so_off],
                                     *(const half2*)&SoLo[so_off]);
                    float2 u = make_float2(0.f, 0.f);
                    if (t >= 0) {
                        size_t uo = ((size_t)(b << 9) + t) * RES + col;
                        u = rec2(*(const half2*)&g_iphi[uo], *(const half2*)&g_iplo[uo]);
                    }
                    float2 v;
                    v.x = 0.7f * so.x + 0.3f * sinf(cx + u.x);
                    v.y = 0.7f * so.y + 0.3f * sinf(cy + u.y);
                    half hx, lx, hy, ly;
                    split16(v.x, hx, lx); split16(v.y, hy, ly);
                    *(half2*)&ShiN[so_off] = __halves2half2(hx, hy);
                    *(half2*)&SloN[so_off] = __halves2half2(lx, ly);
                    if (s >= 2) {
                        size_t ro = ((size_t)(b << 9) + t) * RES + col;
                        *(half2*)&g_rshi[ro] = __halves2half2(hx, hy);
                        *(half2*)&g_rslo[ro] = __halves2half2(lx, ly);
                    }
                } else if (mode == 1) {
                    float* Abm = g_A + (size_t)blockIdx.z * TLEN * TLEN;
                    float2 v;
                    v.x = cx + 1.0f + ((grow == col + 0) ? regc : 0.f);
                    v.y = cy + 1.0f + ((grow == col + 1) ? regc : 0.f);
                    *(float2*)&Abm[(size_t)grow * TLEN + col] = v;
                } else {
                    half hx, lx, hy, ly;
                    split16(cx, hx, lx); split16(cy, hy, ly);
                    size_t off = (size_t)grow * RES + col;
                    *(half2*)&g_iphi[off] = __halves2half2(hx, hy);
                    *(half2*)&g_iplo[off] = __halves2half2(lx, ly);
                }
            }
}

/* ============ split+transpose weights: dst[c][r] = split(src[r][c]) ======= */
__global__ void split_trans_kernel(const float* __restrict__ src, int rows, int cols, int which)
{
    half* dh = which ? g_WinHi : g_Whi;
    half* dl = which ? g_WinLo : g_Wlo;
    __shared__ float t[32][33];
    int c0 = blockIdx.x * 32, r0 = blockIdx.y * 32;
    for (int j = threadIdx.y; j < 32; j += 8)
        t[j][threadIdx.x] = src[(size_t)(r0 + j) * cols + c0 + threadIdx.x];
    __syncthreads();
    for (int j = threadIdx.y; j < 32; j += 8) {
        float f = t[threadIdx.x][j];
        half h, l; split16(f, h, l);
        size_t o = (size_t)(c0 + j) * rows + r0 + threadIdx.x;
        dh[o] = h; dl[o] = l;
    }
}

/* ============ split input rows (no transpose) ============================= */
__global__ void split_input_kernel(const float* __restrict__ src)
{
    int idx = blockIdx.x * 256 + threadIdx.x;
    float f = src[idx];
    half h, l; split16(f, h, l);
    g_xhi[idx] = h; g_xlo[idx] = l;
}

/* =================== step s=0 (state was zero), half2-wide ================ */
__global__ __launch_bounds__(256) void init0_kernel()
{
    int idx = blockIdx.x * 256 + threadIdx.x;
    int row = idx >> 10, q2 = (idx & 1023) * 2;
    int b = row >> 7, w = row & 127;
    int t = 4 * w - 2;
    half2 ph = __float2half2_rn(0.f), pl = ph;
    if (t >= 0) {
        size_t uo = ((size_t)(b << 9) + t) * RES + q2;
        float2 u = rec2(*(const half2*)&g_iphi[uo], *(const half2*)&g_iplo[uo]);
        float vx = 0.3f * sinf(u.x), vy = 0.3f * sinf(u.y);
        half hx, lx, hy, ly;
        split16(vx, hx, lx); split16(vy, hy, ly);
        ph = __halves2half2(hx, hy); pl = __halves2half2(lx, ly);
    }
    size_t so = (size_t)row * RES + q2;
    *(half2*)&g_Shi0[so] = ph;
    *(half2*)&g_Slo0[so] = pl;
}

/* ============ blocked Cholesky, NB=64; also emits LT for its column block = */
__global__ __launch_bounds__(256) void chol_panel_kernel(int p)
{
    const int b = blockIdx.x;
    float* Ab = g_A + (size_t)b * TLEN * TLEN;
    float* Lt = g_LT + (size_t)b * TLEN * TLEN;
    const int jb = p * 64;
    __shared__ float L11[64][65];
    __shared__ float diag[64];
    const int tid = threadIdx.x;
    for (int idx = tid; idx < 64 * 64; idx += 256) {
        int r = idx >> 6, c = idx & 63;
        L11[r][c] = Ab[(jb + r) * TLEN + jb + c];
    }
    __syncthreads();
    for (int k = 0; k < 64; k++) {
        float sq = sqrtf(L11[k][k]);
        if (tid == k) diag[k] = sq;
        if (tid > k && tid < 64) L11[tid][k] /= sq;
        __syncthreads();
        for (int idx = tid; idx < 64 * 64; idx += 256) {
            int r = idx >> 6, c = idx & 63;
            if (r > k && c > k && c <= r) L11[r][c] -= L11[r][k] * L11[c][k];
        }
        __syncthreads();
    }
    for (int idx = tid; idx < 64 * 64; idx += 256) {
        int r = idx >> 6, c = idx & 63;
        float v = (c < r) ? L11[r][c] : (c == r ? diag[r] : 0.f);
        if (c <= r) {
            Ab[(jb + r) * TLEN + jb + c] = v;
            Lt[(size_t)(jb + c) * TLEN + jb + r] = v;
        }
    }
    __syncthreads();
    const int mrows = TLEN - jb - 64;
    for (int r = tid; r < mrows; r += 256) {
        int i = jb + 64 + r;
        float a[64];
        #pragma unroll
        for (int c = 0; c < 64; c++) a[c] = Ab[i * TLEN + jb + c];
        #pragma unroll
        for (int k = 0; k < 64; k++) {
            float sv = a[k];
            #pragma unroll
            for (int q = 0; q < k; q++) sv -= a[q] * L11[k][q];
            a[k] = sv / diag[k];
        }
        #pragma unroll
        for (int c = 0; c < 64; c++) {
            Ab[i * TLEN + jb + c] = a[c];
            Lt[(size_t)(jb + c) * TLEN + i] = a[c];
        }
    }
}

__global__ __launch_bounds__(256) void chol_update_kernel(int p)
{
    const int jb = p * 64 + 64;
    int idx = blockIdx.x;
    int ti = 0;
    while ((ti + 1) * (ti + 2) / 2 <= idx) ti++;
    int tj = idx - ti * (ti + 1) / 2;
    const int b = blockIdx.y;
    float* Ab = g_A + (size_t)b * TLEN * TLEN;
    const int r0 = jb + ti * 64, c0 = jb + tj * 64;
    __shared__ float La[64][65], Lb[64][65];
    const int tid = threadIdx.x;
    for (int q = tid; q < 64 * 64; q += 256) {
        int r = q >> 6, c = q & 63;
        La[r][c] = Ab[(r0 + r) * TLEN + p * 64 + c];
        Lb[r][c] = Ab[(c0 + r) * TLEN + p * 64 + c];
    }
    __syncthreads();
    const int tx = tid & 15, ty = tid >> 4;
    float acc[4][4] = {};
    #pragma unroll
    for (int k = 0; k < 64; k++) {
        float ar[4], bc[4];
        #pragma unroll
        for (int i = 0; i < 4; i++) ar[i] = La[ty * 4 + i][k];
        #pragma unroll
        for (int j = 0; j < 4; j++) bc[j] = Lb[tx * 4 + j][k];
        #pragma unroll
        for (int i = 0; i < 4; i++)
            #pragma unroll
            for (int j = 0; j < 4; j++)
                acc[i][j] += ar[i] * bc[j];
    }
    #pragma unroll
    for (int i = 0; i < 4; i++)
        #pragma unroll
        for (int j = 0; j < 4; j++)
            Ab[(r0 + ty * 4 + i) * TLEN + c0 + tx * 4 + j] -= acc[i][j];
}

/* ============ triangular solves: RHS split 16-way; fused bias =============
   grid = BATCH*16; block bg handles RHS columns [bg*4, bg*4+4).
   Same sequential j-loop and per-column order -> bit-identical g_Z.
   After backward pass, a deterministic tree reduction emits bias directly. */
#define RHSG 4
__global__ __launch_bounds__(512) void solve_kernel(const float* __restrict__ Y,
                                                    float* __restrict__ out)
{
    const int b = blockIdx.x >> 4;
    const int o0 = (blockIdx.x & 15) * RHSG;
    const int i = threadIdx.x;
    const float* __restrict__ Ab = g_A + (size_t)b * TLEN * TLEN;
    const float* __restrict__ Lt = g_LT + (size_t)b * TLEN * TLEN;
    float acc[RHSG];
    #pragma unroll
    for (int o = 0; o < RHSG; o++) acc[o] = Y[((size_t)b * TLEN + i) * OUTD + o0 + o];
    __shared__ float zrow[RHSG];
    for (int j = 0; j < TLEN; j++) {
        if (i == j) {
            float dinv = 1.f / Ab[j * TLEN + j];
            #pragma unroll
            for (int o = 0; o < RHSG; o++) { acc[o] *= dinv; zrow[o] = acc[o]; }
        }
        __syncthreads();
        if (i > j) {
            float lij = Lt[j * TLEN + i];
            #pragma unroll
            for (int o = 0; o < RHSG; o++) acc[o] -= lij * zrow[o];
        }
        __syncthreads();
    }
    for (int j = TLEN - 1; j >= 0; j--) {
        if (i == j) {
            float dinv = 1.f / Ab[j * TLEN + j];
            #pragma unroll
            for (int o = 0; o < RHSG; o++) { acc[o] *= dinv; zrow[o] = acc[o]; }
        }
        __syncthreads();
        if (i < j) {
            float lji = Ab[j * TLEN + i];
            #pragma unroll
            for (int o = 0; o < RHSG; o++) acc[o] -= lji * zrow[o];
        }
        __syncthreads();
    }
    #pragma unroll
    for (int o = 0; o < RHSG; o++) g_Z[((size_t)b * TLEN + i) * OUTD + o0 + o] = acc[o];

    /* fused bias: bias[b][o0+o] = sum_i acc[o] (deterministic tree) */
    __shared__ float red[512];
    #pragma unroll
    for (int o = 0; o < RHSG; o++) {
        __syncthreads();
        red[i] = acc[o];
        __syncthreads();
        #pragma unroll
        for (int sft = 256; sft > 0; sft >>= 1) {
            if (i < sft) red[i] += red[i + sft];
            __syncthreads();
        }
        if (i == 0)
            out[(size_t)BATCH * RES * OUTD + b * OUTD + o0 + o] = red[0];
    }
}

/* ============ W = Xb^T Z  (2048 x 64, K=512), X from rs planes ============ */
__global__ __launch_bounds__(256) void wout_kernel(float* __restrict__ out)
{
    const int b = blockIdx.y;
    const half* __restrict__ Xh = g_rshi + (size_t)b * TLEN * RES;
    const half* __restrict__ Xl = g_rslo + (size_t)b * TLEN * RES;
    const float* __restrict__ Zb = g_Z + (size_t)b * TLEN * OUTD;
    const int d0 = blockIdx.x * 128;
    __shared__ float As2[16][132];
    __shared__ float Bs2[16][68];
    const int tid = threadIdx.x;
    const int lr = tid >> 4, lc = (tid & 15) * 4;
    const int ty = tid >> 4, tx = tid & 15;
    float acc[8][4] = {};
    for (int k0 = 0; k0 < TLEN; k0 += 16) {
        #pragma unroll
        for (int half64 = 0; half64 < 2; half64++) {
            size_t off = (size_t)(k0 + lr) * RES + d0 + lc + half64 * 64;
            half2 h0 = *(const half2*)&Xh[off],     h1 = *(const half2*)&Xh[off + 2];
            half2 l0 = *(const half2*)&Xl[off],     l1 = *(const half2*)&Xl[off + 2];
            float2 a0 = rec2(h0, l0), a1 = rec2(h1, l1);
            As2[lr][lc + half64 * 64 + 0] = a0.x;
            As2[lr][lc + half64 * 64 + 1] = a0.y;
            As2[lr][lc + half64 * 64 + 2] = a1.x;
            As2[lr][lc + half64 * 64 + 3] = a1.y;
        }
        *(float4*)&Bs2[lr][lc] = *(const float4*)&Zb[(k0 + lr) * OUTD + lc];
        __syncthreads();
        #pragma unroll
        for (int k = 0; k < 16; k++) {
            float fa[8], fb[4];
            *(float4*)&fa[0] = *(const float4*)&As2[k][ty * 8];
            *(float4*)&fa[4] = *(const float4*)&As2[k][ty * 8 + 4];
            *(float4*)&fb[0] = *(const float4*)&Bs2[k][tx * 4];
            #pragma unroll
            for (int i = 0; i < 8; i++)
                #pragma unroll
                for (int j = 0; j < 4; j++)
                    acc[i][j] += fa[i] * fb[j];
        }
        __syncthreads();
    }
    #pragma unroll
    for (int i = 0; i < 8; i++)
        #pragma unroll
        for (int j = 0; j < 4; j++)
            out[((size_t)b * RES + d0 + ty * 8 + i) * OUTD + tx * 4 + j] = acc[i][j];
}

/* ======================= launch ======================= */
extern "C" void kernel_launch(void* const* d_in, const int* in_sizes, int n_in,
                              void* d_out, int out_size)
{
    const float* input  = (const float*)d_in[0];
    const float* target = (const float*)d_in[1];
    const float* W_res  = (const float*)d_in[2];
    const float* W_in   = (const float*)d_in[3];
    const float* lam    = (const float*)d_in[4];
    float* out = (float*)d_out;

    cudaFuncSetAttribute(tc_kernel, cudaFuncAttributeMaxDynamicSharedMemorySize, SMEM_DYN);

    /* 0. split+transpose weights, split input */
    split_trans_kernel<<<dim3(RES / 32, RES / 32), dim3(32, 8)>>>(W_res, RES, RES, 0);
    split_trans_kernel<<<dim3(RES / 32, INDIM / 32), dim3(32, 8)>>>(W_in, INDIM, RES, 1);
    split_input_kernel<<<(NROWS * INDIM) / 256, 256>>>(input);

    /* 1. input projection (writes inproj planes) */
    tc_kernel<<<dim3(RES / 128, NROWS / 128), 256, SMEM_DYN>>>(2, 0, 0, nullptr);

    /* 2. reservoir (state lives only as hi/lo planes) */
    init0_kernel<<<(MROWS * RES / 2) / 256, 256>>>();
    int flip = 0;
    for (int s = 1; s <= 5; s++) {
        tc_kernel<<<dim3(RES / 128, MROWS / 128), 256, SMEM_DYN>>>(0, s, flip, nullptr);
        flip ^= 1;
    }

    /* 3. gram: 10 lower (128x128) tiles; diag tiles dedup B loads */
    tc_kernel<<<dim3(10, 1, BATCH), 256, SMEM_DYN>>>(1, 0, 0, lam);

    /* 4. batched blocked Cholesky (panel also emits LT column block) */
    for (int p = 0; p < 8; p++) {
        chol_panel_kernel<<<BATCH, 256>>>(p);
        if (p < 7) {
            int mt = 7 - p;
            chol_update_kernel<<<dim3(mt * (mt + 1) / 2, BATCH), 256>>>(p);
        }
    }

    /* 5. triangular solves (16-way RHS split) + fused bias */
    solve_kernel<<<BATCH * 16, 512>>>(target, out);

    /* 6. readout weights */
    wout_kernel<<<dim3(RES / 128, BATCH), 256>>>(out);

    (void)in_sizes; (void)n_in; (void)out_size;
}

// round 16
// speedup vs baseline: 1.4245x; 1.1188x over previous
#include <cuda_runtime.h>
#include <cuda_fp16.h>
#include <math.h>
#include <stdint.h>

#define BATCH 32
#define TLEN  512
#define INDIM 128
#define RES   2048
#define OUTD  64
#define NWIN  128
#define MROWS (BATCH*NWIN)   /* 4096  reservoir rows (b,w) */
#define NROWS (BATCH*TLEN)   /* 16384 time rows (b,t)      */

/* ---------------- scratch (device globals; no allocations) ---------------- */
__device__ float g_A[BATCH * TLEN * TLEN]; /* gram matrices          32 MB */
__device__ float g_LT[BATCH * TLEN * TLEN];/* L transposed           32 MB */
__device__ float g_Z[BATCH * TLEN * OUTD]; /* solve result            4 MB */
/* fp16 split planes (hi+lo reconstructs fp32 to ~2^-22) */
__device__ half g_Shi0[MROWS * RES], g_Slo0[MROWS * RES];   /* state ping */
__device__ half g_Shi1[MROWS * RES], g_Slo1[MROWS * RES];   /* state pong */
__device__ half g_rshi[NROWS * RES], g_rslo[NROWS * RES];   /* rs states  */
__device__ half g_iphi[NROWS * RES], g_iplo[NROWS * RES];   /* inproj     */
__device__ half g_Whi[RES * RES],   g_Wlo[RES * RES];       /* WresT      */
__device__ half g_WinHi[RES * INDIM], g_WinLo[RES * INDIM]; /* WinT       */
__device__ half g_xhi[NROWS * INDIM], g_xlo[NROWS * INDIM]; /* input      */

/* ====================== helpers ====================== */
__device__ __forceinline__ uint32_t smem_u32(const void* p) {
    uint32_t a;
    asm("{ .reg .u64 t; cvta.to.shared.u64 t, %1; cvt.u32.u64 %0, t; }" : "=r"(a) : "l"(p));
    return a;
}
__device__ __forceinline__ void cpasync16(uint32_t dst, const void* src) {
    asm volatile("cp.async.cg.shared.global [%0], [%1], 16;" :: "r"(dst), "l"(src));
}
__device__ __forceinline__ void cp_commit() { asm volatile("cp.async.commit_group;" ::: "memory"); }
__device__ __forceinline__ void cp_wait1()  { asm volatile("cp.async.wait_group 1;" ::: "memory"); }
__device__ __forceinline__ void cp_wait0()  { asm volatile("cp.async.wait_group 0;" ::: "memory"); }

__device__ __forceinline__ void ldsm4(uint32_t* r, uint32_t addr) {
    asm volatile("ldmatrix.sync.aligned.m8n8.x4.shared.b16 {%0,%1,%2,%3}, [%4];"
        : "=r"(r[0]), "=r"(r[1]), "=r"(r[2]), "=r"(r[3]) : "r"(addr));
}
__device__ __forceinline__ void mma16816(float* d, const uint32_t* a, uint32_t b0, uint32_t b1) {
    asm volatile(
        "mma.sync.aligned.m16n8k16.row.col.f32.f16.f16.f32 "
        "{%0,%1,%2,%3},{%4,%5,%6,%7},{%8,%9},{%0,%1,%2,%3};"
        : "+f"(d[0]), "+f"(d[1]), "+f"(d[2]), "+f"(d[3])
        : "r"(a[0]), "r"(a[1]), "r"(a[2]), "r"(a[3]), "r"(b0), "r"(b1));
}
__device__ __forceinline__ void split16(float f, half& h, half& l) {
    h = __float2half_rn(f);
    l = __float2half_rn(f - __half2float(h));
}
__device__ __forceinline__ float2 rec2(half2 h, half2 l) {
    float2 fh = __half22float2(h), fl = __half22float2(l);
    return make_float2(fh.x + fl.x, fh.y + fl.y);
}

/* ============ fp16x3 GEMM kernel (mma.sync m16n8k16) ====================== */
#define A_PLANE 8192
#define B_PLANE 8192
#define STAGE_B 32768
#define SMEM_DYN (3*STAGE_B)   /* 98304 */

__global__ __launch_bounds__(256, 2) void tc_kernel(
    int mode, int s, int flip, const float* __restrict__ lam)
{
    extern __shared__ char smem[];
    const uint32_t smem_u = smem_u32(smem);

    const int tid = threadIdx.x;
    const int wid = tid >> 5, lane = tid & 31;
    const int gid = lane >> 2, tig = lane & 3;
    const int m = lane >> 3, l7 = lane & 7;
    const int warpM = wid >> 2, warpN = wid & 3;
    const int rowBase = warpM * 64, colBase = warpN * 32;

    int row0, col0;
    if (mode == 1) {
        int x = blockIdx.x, ti = 0;
        while ((ti + 1) * (ti + 2) / 2 <= x) ti++;
        int tj = x - ti * (ti + 1) / 2;
        row0 = ti * 128; col0 = tj * 128;
    } else {
        row0 = blockIdx.y * 128; col0 = blockIdx.x * 128;
    }
    const int diag = (mode == 1) && (row0 == col0);   /* A tile == B tile */

    const half *Ahi, *Alo, *Bhi, *Blo; int K;
    if (mode == 0) {
        Ahi = flip ? g_Shi1 : g_Shi0; Alo = flip ? g_Slo1 : g_Slo0;
        Bhi = g_Whi; Blo = g_Wlo; K = RES;
    } else if (mode == 1) {
        size_t base = (size_t)blockIdx.z * TLEN * RES;
        Ahi = g_rshi + base; Alo = g_rslo + base;
        Bhi = Ahi; Blo = Alo; K = RES;
    } else {
        Ahi = g_xhi; Alo = g_xlo; Bhi = g_WinHi; Blo = g_WinLo; K = INDIM;
    }
    const int nIter = K >> 5;

    float acc[4][4][4] = {};

    uint32_t aRB[4], aX[4], bRB[2], bX[2];
    #pragma unroll
    for (int mt = 0; mt < 4; mt++) {
        uint32_t r = rowBase + mt * 16 + (m & 1) * 8 + l7;
        aRB[mt] = r * 64; aX[mt] = (r >> 1) & 3;
    }
    #pragma unroll
    for (int np = 0; np < 2; np++) {
        uint32_t n = colBase + (np * 2 + (m >> 1)) * 8 + l7;
        bRB[np] = n * 64; bX[np] = (n >> 1) & 3;
    }
    const uint32_t amk = (uint32_t)(m >> 1);
    const uint32_t bmk = (uint32_t)(m & 1);

    auto load_chunk = [&](int it, int stage) {
        const int k0 = it << 5;
        const uint32_t sb = smem_u + (uint32_t)stage * STAGE_B;
        #pragma unroll
        for (int q = 0; q < 8; q++) {
            int idx = tid + q * 256;
            int op = idx >> 10;
            if (diag && op) continue;          /* B aliases A for diag tiles */
            int j = idx & 1023;
            int p = j >> 9, r = (j >> 2) & 127, c = j & 3;
            const half* gp = op ? (p ? Blo : Bhi) : (p ? Alo : Ahi);
            int rowg = (op ? col0 : row0) + r;
            const half* src = gp + (size_t)rowg * K + k0 + c * 8;
            uint32_t dst = sb + (uint32_t)op * (2 * A_PLANE) + (uint32_t)p * A_PLANE
                         + (uint32_t)r * 64 + (uint32_t)((c ^ ((r >> 1) & 3)) * 16);
            cpasync16(dst, src);
        }
    };

    load_chunk(0, 0);
    cp_commit();
    if (nIter > 1) { load_chunk(1, 1); cp_commit(); }

    for (int it = 0; it < nIter; ++it) {
        if (it + 1 < nIter) cp_wait1(); else cp_wait0();
        __syncthreads();
        if (it + 2 < nIter) { load_chunk(it + 2, (it + 2) % 3); cp_commit(); }

        const uint32_t sb = smem_u + (uint32_t)(it % 3) * STAGE_B;
        const uint32_t pAh = sb, pAl = sb + A_PLANE;
        const uint32_t pBh = diag ? pAh : sb + 2 * A_PLANE;
        const uint32_t pBl = diag ? pAl : sb + 2 * A_PLANE + B_PLANE;
        #pragma unroll
        for (int h16 = 0; h16 < 2; h16++) {
            uint32_t bh[2][4], bl[2][4];
            #pragma unroll
            for (int np = 0; np < 2; np++) {
                uint32_t off = bRB[np] + (((h16 * 2 + bmk) ^ bX[np]) * 16);
                ldsm4(bh[np], pBh + off);
                ldsm4(bl[np], pBl + off);
            }
            #pragma unroll
            for (int mt = 0; mt < 4; mt++) {
                uint32_t ah[4], al[4];
                uint32_t off = aRB[mt] + (((h16 * 2 + amk) ^ aX[mt]) * 16);
                ldsm4(ah, pAh + off);
                ldsm4(al, pAl + off);
                #pragma unroll
                for (int nt = 0; nt < 4; nt++) {
                    uint32_t b0h = bh[nt >> 1][(nt & 1) * 2], b1h = bh[nt >> 1][(nt & 1) * 2 + 1];
                    uint32_t b0l = bl[nt >> 1][(nt & 1) * 2], b1l = bl[nt >> 1][(nt & 1) * 2 + 1];
                    mma16816(acc[mt][nt], ah, b0h, b1h);
                    mma16816(acc[mt][nt], ah, b0l, b1l);
                    mma16816(acc[mt][nt], al, b0h, b1h);
                }
            }
        }
    }

    /* -------------------- epilogue (register -> global, planes only) ------- */
    float regc = 0.f;
    if (mode == 1) { float l = lam[0]; regc = log1pf(expf(l)); }
    const half* SoHi = flip ? g_Shi1 : g_Shi0;
    const half* SoLo = flip ? g_Slo1 : g_Slo0;
    half* ShiN = flip ? g_Shi0 : g_Shi1;
    half* SloN = flip ? g_Slo0 : g_Slo1;

    #pragma unroll
    for (int mt = 0; mt < 4; mt++)
        #pragma unroll
        for (int nt = 0; nt < 4; nt++)
            #pragma unroll
            for (int h = 0; h < 2; h++) {
                int grow = row0 + rowBase + mt * 16 + gid + h * 8;
                int col = col0 + colBase + nt * 8 + tig * 2;
                float cx = acc[mt][nt][h * 2 + 0];
                float cy = acc[mt][nt][h * 2 + 1];
                if (mode == 0) {
                    int b = grow >> 7, w = grow & 127;
                    int t = 4 * w + s - 2;
                    size_t so_off = (size_t)grow * RES + col;
                    float2 so = rec2(*(const half2*)&SoHi[so_off],
                                     *(const half2*)&SoLo[so_off]);
                    float2 u = make_float2(0.f, 0.f);
                    if (t >= 0) {
                        size_t uo = ((size_t)(b << 9) + t) * RES + col;
                        u = rec2(*(const half2*)&g_iphi[uo], *(const half2*)&g_iplo[uo]);
                    }
                    float2 v;
                    v.x = 0.7f * so.x + 0.3f * sinf(cx + u.x);
                    v.y = 0.7f * so.y + 0.3f * sinf(cy + u.y);
                    half hx, lx, hy, ly;
                    split16(v.x, hx, lx); split16(v.y, hy, ly);
                    if (s < 5) {               /* final state never re-read */
                        *(half2*)&ShiN[so_off] = __halves2half2(hx, hy);
                        *(half2*)&SloN[so_off] = __halves2half2(lx, ly);
                    }
                    if (s >= 2) {
                        size_t ro = ((size_t)(b << 9) + t) * RES + col;
                        *(half2*)&g_rshi[ro] = __halves2half2(hx, hy);
                        *(half2*)&g_rslo[ro] = __halves2half2(lx, ly);
                    }
                } else if (mode == 1) {
                    float* Abm = g_A + (size_t)blockIdx.z * TLEN * TLEN;
                    float2 v;
                    v.x = cx + 1.0f + ((grow == col + 0) ? regc : 0.f);
                    v.y = cy + 1.0f + ((grow == col + 1) ? regc : 0.f);
                    *(float2*)&Abm[(size_t)grow * TLEN + col] = v;
                } else {
                    half hx, lx, hy, ly;
                    split16(cx, hx, lx); split16(cy, hy, ly);
                    size_t off = (size_t)grow * RES + col;
                    *(half2*)&g_iphi[off] = __halves2half2(hx, hy);
                    *(half2*)&g_iplo[off] = __halves2half2(lx, ly);
                }
            }
}

/* ============ split+transpose weights: dst[c][r] = split(src[r][c]) ======= */
__global__ void split_trans_kernel(const float* __restrict__ src, int rows, int cols, int which)
{
    half* dh = which ? g_WinHi : g_Whi;
    half* dl = which ? g_WinLo : g_Wlo;
    __shared__ float t[32][33];
    int c0 = blockIdx.x * 32, r0 = blockIdx.y * 32;
    for (int j = threadIdx.y; j < 32; j += 8)
        t[j][threadIdx.x] = src[(size_t)(r0 + j) * cols + c0 + threadIdx.x];
    __syncthreads();
    for (int j = threadIdx.y; j < 32; j += 8) {
        float f = t[threadIdx.x][j];
        half h, l; split16(f, h, l);
        size_t o = (size_t)(c0 + j) * rows + r0 + threadIdx.x;
        dh[o] = h; dl[o] = l;
    }
}

/* ============ split input rows (no transpose) ============================= */
__global__ void split_input_kernel(const float* __restrict__ src)
{
    int idx = blockIdx.x * 256 + threadIdx.x;
    float f = src[idx];
    half h, l; split16(f, h, l);
    g_xhi[idx] = h; g_xlo[idx] = l;
}

/* =================== step s=0 (state was zero), half2-wide ================ */
__global__ __launch_bounds__(256) void init0_kernel()
{
    int idx = blockIdx.x * 256 + threadIdx.x;
    int row = idx >> 10, q2 = (idx & 1023) * 2;
    int b = row >> 7, w = row & 127;
    int t = 4 * w - 2;
    half2 ph = __float2half2_rn(0.f), pl = ph;
    if (t >= 0) {
        size_t uo = ((size_t)(b << 9) + t) * RES + q2;
        float2 u = rec2(*(const half2*)&g_iphi[uo], *(const half2*)&g_iplo[uo]);
        float vx = 0.3f * sinf(u.x), vy = 0.3f * sinf(u.y);
        half hx, lx, hy, ly;
        split16(vx, hx, lx); split16(vy, hy, ly);
        ph = __halves2half2(hx, hy); pl = __halves2half2(lx, ly);
    }
    size_t so = (size_t)row * RES + q2;
    *(half2*)&g_Shi0[so] = ph;
    *(half2*)&g_Slo0[so] = pl;
}

/* ============ blocked Cholesky, NB=64; also emits LT for its column block = */
__global__ __launch_bounds__(256) void chol_panel_kernel(int p)
{
    const int b = blockIdx.x;
    float* Ab = g_A + (size_t)b * TLEN * TLEN;
    float* Lt = g_LT + (size_t)b * TLEN * TLEN;
    const int jb = p * 64;
    __shared__ float L11[64][65];
    __shared__ float diag[64];
    const int tid = threadIdx.x;
    for (int idx = tid; idx < 64 * 64; idx += 256) {
        int r = idx >> 6, c = idx & 63;
        L11[r][c] = Ab[(jb + r) * TLEN + jb + c];
    }
    __syncthreads();
    for (int k = 0; k < 64; k++) {
        float sq = sqrtf(L11[k][k]);
        if (tid == k) diag[k] = sq;
        if (tid > k && tid < 64) L11[tid][k] /= sq;
        __syncthreads();
        for (int idx = tid; idx < 64 * 64; idx += 256) {
            int r = idx >> 6, c = idx & 63;
            if (r > k && c > k && c <= r) L11[r][c] -= L11[r][k] * L11[c][k];
        }
        __syncthreads();
    }
    for (int idx = tid; idx < 64 * 64; idx += 256) {
        int r = idx >> 6, c = idx & 63;
        float v = (c < r) ? L11[r][c] : (c == r ? diag[r] : 0.f);
        if (c <= r) {
            Ab[(jb + r) * TLEN + jb + c] = v;
            Lt[(size_t)(jb + c) * TLEN + jb + r] = v;
        }
    }
    __syncthreads();
    const int mrows = TLEN - jb - 64;
    for (int r = tid; r < mrows; r += 256) {
        int i = jb + 64 + r;
        float a[64];
        #pragma unroll
        for (int c = 0; c < 64; c++) a[c] = Ab[i * TLEN + jb + c];
        #pragma unroll
        for (int k = 0; k < 64; k++) {
            float sv = a[k];
            #pragma unroll
            for (int q = 0; q < k; q++) sv -= a[q] * L11[k][q];
            a[k] = sv / diag[k];
        }
        #pragma unroll
        for (int c = 0; c < 64; c++) {
            Ab[i * TLEN + jb + c] = a[c];
            Lt[(size_t)(jb + c) * TLEN + i] = a[c];
        }
    }
}

__global__ __launch_bounds__(256) void chol_update_kernel(int p)
{
    const int jb = p * 64 + 64;
    int idx = blockIdx.x;
    int ti = 0;
    while ((ti + 1) * (ti + 2) / 2 <= idx) ti++;
    int tj = idx - ti * (ti + 1) / 2;
    const int b = blockIdx.y;
    float* Ab = g_A + (size_t)b * TLEN * TLEN;
    const int r0 = jb + ti * 64, c0 = jb + tj * 64;
    __shared__ float La[64][65], Lb[64][65];
    const int tid = threadIdx.x;
    for (int q = tid; q < 64 * 64; q += 256) {
        int r = q >> 6, c = q & 63;
        La[r][c] = Ab[(r0 + r) * TLEN + p * 64 + c];
        Lb[r][c] = Ab[(c0 + r) * TLEN + p * 64 + c];
    }
    __syncthreads();
    const int tx = tid & 15, ty = tid >> 4;
    float acc[4][4] = {};
    #pragma unroll
    for (int k = 0; k < 64; k++) {
        float ar[4], bc[4];
        #pragma unroll
        for (int i = 0; i < 4; i++) ar[i] = La[ty * 4 + i][k];
        #pragma unroll
        for (int j = 0; j < 4; j++) bc[j] = Lb[tx * 4 + j][k];
        #pragma unroll
        for (int i = 0; i < 4; i++)
            #pragma unroll
            for (int j = 0; j < 4; j++)
                acc[i][j] += ar[i] * bc[j];
    }
    #pragma unroll
    for (int i = 0; i < 4; i++)
        #pragma unroll
        for (int j = 0; j < 4; j++)
            Ab[(r0 + ty * 4 + i) * TLEN + c0 + tx * 4 + j] -= acc[i][j];
}

/* ============ triangular solves: warp-diagonal + block-bulk ===============
   grid = BATCH*16; block bg handles RHS columns [bg*4, bg*4+4).
   Rows [base, base+32) of the block ARE one warp: the 32-row diagonal solve
   runs warp-locally with shfl broadcasts (no divergent barriers); one plain
   __syncthreads publishes z; trailing update runs barrier-free in bulk.
   Per-element update order identical to sequential -> bit-identical g_Z.  */
#define RHSG 4
__global__ __launch_bounds__(512) void solve_kernel(const float* __restrict__ Y,
                                                    float* __restrict__ out)
{
    const int b = blockIdx.x >> 4;
    const int o0 = (blockIdx.x & 15) * RHSG;
    const int i = threadIdx.x;
    const int lane = i & 31, wrp = i >> 5;
    const float* __restrict__ Ab = g_A + (size_t)b * TLEN * TLEN;
    const float* __restrict__ Lt = g_LT + (size_t)b * TLEN * TLEN;
    float acc[RHSG];
    #pragma unroll
    for (int o = 0; o < RHSG; o++) acc[o] = Y[((size_t)b * TLEN + i) * OUTD + o0 + o];
    __shared__ float zs[32][RHSG];
    __shared__ float Ls[32][33];

    /* ---------------- forward: L w = y ---------------- */
    for (int mb = 0; mb < 16; mb++) {
        const int base = mb * 32;
        if (wrp == mb) {
            #pragma unroll 8
            for (int k = 0; k < 32; k++)
                Ls[k][lane] = Lt[(size_t)(base + k) * TLEN + base + lane];
            __syncwarp();
            for (int k = 0; k < 32; k++) {
                if (lane == k) {
                    float dinv = 1.f / Ls[k][k];
                    #pragma unroll
                    for (int o = 0; o < RHSG; o++) acc[o] *= dinv;
                }
                float zk[RHSG];
                #pragma unroll
                for (int o = 0; o < RHSG; o++) zk[o] = __shfl_sync(0xffffffffu, acc[o], k);
                if (lane > k) {
                    float lij = Ls[k][lane];
                    #pragma unroll
                    for (int o = 0; o < RHSG; o++) acc[o] -= lij * zk[o];
                }
                if (lane == k) {
                    #pragma unroll
                    for (int o = 0; o < RHSG; o++) zs[k][o] = acc[o];
                }
            }
        }
        __syncthreads();
        if (i >= base + 32) {
            #pragma unroll 4
            for (int k = 0; k < 32; k++) {
                float lij = Lt[(size_t)(base + k) * TLEN + i];
                #pragma unroll
                for (int o = 0; o < RHSG; o++) acc[o] -= lij * zs[k][o];
            }
        }
        __syncthreads();
    }

    /* ---------------- backward: L^T z = w ---------------- */
    for (int mb = 15; mb >= 0; mb--) {
        const int base = mb * 32;
        if (wrp == mb) {
            #pragma unroll 8
            for (int k = 0; k < 32; k++)
                Ls[k][lane] = Ab[(size_t)(base + k) * TLEN + base + lane];
            __syncwarp();
            for (int k = 31; k >= 0; k--) {
                if (lane == k) {
                    float dinv = 1.f / Ls[k][k];
                    #pragma unroll
                    for (int o = 0; o < RHSG; o++) acc[o] *= dinv;
                }
                float zk[RHSG];
                #pragma unroll
                for (int o = 0; o < RHSG; o++) zk[o] = __shfl_sync(0xffffffffu, acc[o], k);
                if (lane < k) {
                    float lji = Ls[k][lane];
                    #pragma unroll
                    for (int o = 0; o < RHSG; o++) acc[o] -= lji * zk[o];
                }
                if (lane == k) {
                    #pragma unroll
                    for (int o = 0; o < RHSG; o++) zs[k][o] = acc[o];
                }
            }
        }
        __syncthreads();
        if (i < base) {
            #pragma unroll 4
            for (int k = 31; k >= 0; k--) {
                float lji = Ab[(size_t)(base + k) * TLEN + i];
                #pragma unroll
                for (int o = 0; o < RHSG; o++) acc[o] -= lji * zs[k][o];
            }
        }
        __syncthreads();
    }
    #pragma unroll
    for (int o = 0; o < RHSG; o++) g_Z[((size_t)b * TLEN + i) * OUTD + o0 + o] = acc[o];

    /* fused bias: bias[b][o0+o] = sum_i acc[o] (deterministic tree) */
    __shared__ float red[512];
    #pragma unroll
    for (int o = 0; o < RHSG; o++) {
        __syncthreads();
        red[i] = acc[o];
        __syncthreads();
        #pragma unroll
        for (int sft = 256; sft > 0; sft >>= 1) {
            if (i < sft) red[i] += red[i + sft];
            __syncthreads();
        }
        if (i == 0)
            out[(size_t)BATCH * RES * OUTD + b * OUTD + o0 + o] = red[0];
    }
}

/* ============ W = Xb^T Z  (2048 x 64, K=512), X from rs planes ============ */
__global__ __launch_bounds__(256) void wout_kernel(float* __restrict__ out)
{
    const int b = blockIdx.y;
    const half* __restrict__ Xh = g_rshi + (size_t)b * TLEN * RES;
    const half* __restrict__ Xl = g_rslo + (size_t)b * TLEN * RES;
    const float* __restrict__ Zb = g_Z + (size_t)b * TLEN * OUTD;
    const int d0 = blockIdx.x * 128;
    __shared__ float As2[16][132];
    __shared__ float Bs2[16][68];
    const int tid = threadIdx.x;
    const int lr = tid >> 4, lc = (tid & 15) * 4;
    const int ty = tid >> 4, tx = tid & 15;
    float acc[8][4] = {};
    for (int k0 = 0; k0 < TLEN; k0 += 16) {
        #pragma unroll
        for (int half64 = 0; half64 < 2; half64++) {
            size_t off = (size_t)(k0 + lr) * RES + d0 + lc + half64 * 64;
            half2 h0 = *(const half2*)&Xh[off],     h1 = *(const half2*)&Xh[off + 2];
            half2 l0 = *(const half2*)&Xl[off],     l1 = *(const half2*)&Xl[off + 2];
            float2 a0 = rec2(h0, l0), a1 = rec2(h1, l1);
            As2[lr][lc + half64 * 64 + 0] = a0.x;
            As2[lr][lc + half64 * 64 + 1] = a0.y;
            As2[lr][lc + half64 * 64 + 2] = a1.x;
            As2[lr][lc + half64 * 64 + 3] = a1.y;
        }
        *(float4*)&Bs2[lr][lc] = *(const float4*)&Zb[(k0 + lr) * OUTD + lc];
        __syncthreads();
        #pragma unroll
        for (int k = 0; k < 16; k++) {
            float fa[8], fb[4];
            *(float4*)&fa[0] = *(const float4*)&As2[k][ty * 8];
            *(float4*)&fa[4] = *(const float4*)&As2[k][ty * 8 + 4];
            *(float4*)&fb[0] = *(const float4*)&Bs2[k][tx * 4];
            #pragma unroll
            for (int i = 0; i < 8; i++)
                #pragma unroll
                for (int j = 0; j < 4; j++)
                    acc[i][j] += fa[i] * fb[j];
        }
        __syncthreads();
    }
    #pragma unroll
    for (int i = 0; i < 8; i++)
        #pragma unroll
        for (int j = 0; j < 4; j++)
            out[((size_t)b * RES + d0 + ty * 8 + i) * OUTD + tx * 4 + j] = acc[i][j];
}

/* ======================= launch ======================= */
extern "C" void kernel_launch(void* const* d_in, const int* in_sizes, int n_in,
                              void* d_out, int out_size)
{
    const float* input  = (const float*)d_in[0];
    const float* target = (const float*)d_in[1];
    const float* W_res  = (const float*)d_in[2];
    const float* W_in   = (const float*)d_in[3];
    const float* lam    = (const float*)d_in[4];
    float* out = (float*)d_out;

    cudaFuncSetAttribute(tc_kernel, cudaFuncAttributeMaxDynamicSharedMemorySize, SMEM_DYN);

    /* 0. split+transpose weights, split input */
    split_trans_kernel<<<dim3(RES / 32, RES / 32), dim3(32, 8)>>>(W_res, RES, RES, 0);
    split_trans_kernel<<<dim3(RES / 32, INDIM / 32), dim3(32, 8)>>>(W_in, INDIM, RES, 1);
    split_input_kernel<<<(NROWS * INDIM) / 256, 256>>>(input);

    /* 1. input projection (writes inproj planes) */
    tc_kernel<<<dim3(RES / 128, NROWS / 128), 256, SMEM_DYN>>>(2, 0, 0, nullptr);

    /* 2. reservoir (state lives only as hi/lo planes) */
    init0_kernel<<<(MROWS * RES / 2) / 256, 256>>>();
    int flip = 0;
    for (int s = 1; s <= 5; s++) {
        tc_kernel<<<dim3(RES / 128, MROWS / 128), 256, SMEM_DYN>>>(0, s, flip, nullptr);
        flip ^= 1;
    }

    /* 3. gram: 10 lower (128x128) tiles; diag tiles dedup B loads */
    tc_kernel<<<dim3(10, 1, BATCH), 256, SMEM_DYN>>>(1, 0, 0, lam);

    /* 4. batched blocked Cholesky (panel also emits LT column block) */
    for (int p = 0; p < 8; p++) {
        chol_panel_kernel<<<BATCH, 256>>>(p);
        if (p < 7) {
            int mt = 7 - p;
            chol_update_kernel<<<dim3(mt * (mt + 1) / 2, BATCH), 256>>>(p);
        }
    }

    /* 5. triangular solves (warp-diagonal) + fused bias */
    solve_kernel<<<BATCH * 16, 512>>>(target, out);

    /* 6. readout weights */
    wout_kernel<<<dim3(RES / 128, BATCH), 256>>>(out);

    (void)in_sizes; (void)n_in; (void)out_size;
}